// round 1
// baseline (speedup 1.0000x reference)
#include <cuda_runtime.h>
#include <math.h>

#define BB 2
#define SS 2048
#define DD 1024
#define HH 16
#define HD 64
#define ROWS (BB*SS)      // 4096
#define TRIPLE (3*HD)     // 192 floats per (row, head)

// Scratch (static device globals; no allocation at runtime)
__device__ float g_qkv[(size_t)ROWS * 3 * DD];   // [ROWS][H][192]
__device__ float g_att[(size_t)ROWS * DD];       // [ROWS][H][64]

// ---------------------------------------------------------------------------
// SGEMM: C[M,N] = A[M,K] @ B[K,N], fp32, 128x128 tile, BK=16, 256 threads,
// 8x8 register blocking per thread. M,N,K multiples of 128/128/16.
// ---------------------------------------------------------------------------
__global__ __launch_bounds__(256) void sgemm_k(const float* __restrict__ A,
                                               const float* __restrict__ Bm,
                                               float* __restrict__ C,
                                               int M, int N, int K)
{
    __shared__ float As[16][128];
    __shared__ float Bs[16][128];
    const int tid = threadIdx.x;
    const int tx = tid & 15;        // N direction (8 cols each)
    const int ty = tid >> 4;        // M direction (8 rows each)
    const float* Ag = A + (size_t)blockIdx.y * 128 * K;
    const float* Bg = Bm + (size_t)blockIdx.x * 128;

    float acc[8][8];
#pragma unroll
    for (int i = 0; i < 8; i++)
#pragma unroll
        for (int j = 0; j < 8; j++) acc[i][j] = 0.f;

    for (int k0 = 0; k0 < K; k0 += 16) {
        // Load A tile 128x16 (512 float4, 2 per thread), store transposed
#pragma unroll
        for (int uu = 0; uu < 2; uu++) {
            int u = tid * 2 + uu;
            int r = u >> 2;
            int c = (u & 3) * 4;
            float4 a = *(const float4*)(Ag + (size_t)r * K + k0 + c);
            As[c + 0][r] = a.x;
            As[c + 1][r] = a.y;
            As[c + 2][r] = a.z;
            As[c + 3][r] = a.w;
        }
        // Load B tile 16x128 (512 float4, 2 per thread)
#pragma unroll
        for (int uu = 0; uu < 2; uu++) {
            int u = tid * 2 + uu;
            int r = u >> 5;
            int c = (u & 31) * 4;
            float4 b = *(const float4*)(Bg + (size_t)(k0 + r) * N + c);
            *(float4*)(&Bs[r][c]) = b;
        }
        __syncthreads();
#pragma unroll
        for (int kk = 0; kk < 16; kk++) {
            float ra[8], rb[8];
#pragma unroll
            for (int i = 0; i < 8; i++) ra[i] = As[kk][ty * 8 + i];
#pragma unroll
            for (int j = 0; j < 8; j++) rb[j] = Bs[kk][tx * 8 + j];
#pragma unroll
            for (int i = 0; i < 8; i++)
#pragma unroll
                for (int j = 0; j < 8; j++) acc[i][j] += ra[i] * rb[j];
        }
        __syncthreads();
    }

    float* Cg = C + (size_t)(blockIdx.y * 128 + ty * 8) * N + blockIdx.x * 128 + tx * 8;
#pragma unroll
    for (int i = 0; i < 8; i++) {
#pragma unroll
        for (int j = 0; j < 8; j += 4) {
            float4 v = make_float4(acc[i][j], acc[i][j + 1], acc[i][j + 2], acc[i][j + 3]);
            *(float4*)(Cg + (size_t)i * N + j) = v;
        }
    }
}

// ---------------------------------------------------------------------------
// RoPE (rotate-half, base 10000) applied in-place to q and k parts of g_qkv.
// Also scales q by 1/sqrt(HD) = 0.125.
// One thread per (row, head, comp in {q,k}, i in [0,32)).
// ---------------------------------------------------------------------------
__global__ void rope_k(const int* __restrict__ pos)
{
    int idx = blockIdx.x * blockDim.x + threadIdx.x;
    const int total = ROWS * HH * 2 * 32;
    if (idx >= total) return;
    int i = idx & 31;
    int rest = idx >> 5;
    int comp = rest & 1; rest >>= 1;   // 0 = q, 1 = k
    int h = rest & 15;
    int row = rest >> 4;

    float p = (float)pos[row];
    float inv = powf(10000.0f, -(float)i * (1.0f / 32.0f));
    float ang = p * inv;
    float sn, cs;
    sincosf(ang, &sn, &cs);

    float* base = g_qkv + ((size_t)row * HH + h) * TRIPLE + comp * HD;
    float x1 = base[i];
    float x2 = base[i + 32];
    float o1 = x1 * cs - x2 * sn;
    float o2 = x1 * sn + x2 * cs;
    if (comp == 0) { o1 *= 0.125f; o2 *= 0.125f; }
    base[i] = o1;
    base[i + 32] = o2;
}

// ---------------------------------------------------------------------------
// Causal flash attention, fp32. grid = (S/128, B*H), 128 threads.
// One thread per query row; K/V tiles (32 x 64) staged in shared memory.
// ---------------------------------------------------------------------------
#define TQ 128
#define TK 32
__global__ __launch_bounds__(128) void flash_k()
{
    __shared__ float Ksh[TK][HD];
    __shared__ float Vsh[TK][HD];
    const int t = threadIdx.x;
    const int b = blockIdx.y >> 4;   // / H
    const int h = blockIdx.y & 15;   // % H
    const int qstart = blockIdx.x * TQ;
    const int qi = qstart + t;
    const int row = b * SS + qi;

    const float* qptr = g_qkv + ((size_t)row * HH + h) * TRIPLE;
    float q[HD];
#pragma unroll
    for (int d = 0; d < HD; d++) q[d] = qptr[d];

    float m = -INFINITY, l = 0.f;
    float acc[HD];
#pragma unroll
    for (int d = 0; d < HD; d++) acc[d] = 0.f;

    const int ntiles = (qstart + TQ) / TK;   // causal bound
    for (int tt = 0; tt < ntiles; tt++) {
        const int k0 = tt * TK;
        // Cooperative load of K and V tiles: 512 float4 each, 4 per thread
#pragma unroll
        for (int uu = 0; uu < 4; uu++) {
            int u = t + uu * 128;
            int j = u >> 4;
            int c = (u & 15) * 4;
            const float* kvbase = g_qkv + ((size_t)(b * SS + k0 + j) * HH + h) * TRIPLE;
            *(float4*)(&Ksh[j][c]) = *(const float4*)(kvbase + HD + c);
            *(float4*)(&Vsh[j][c]) = *(const float4*)(kvbase + 2 * HD + c);
        }
        __syncthreads();

        float sc[TK];
#pragma unroll
        for (int j = 0; j < TK; j++) {
            float s_ = 0.f;
#pragma unroll
            for (int d = 0; d < HD; d++) s_ += q[d] * Ksh[j][d];
            sc[j] = (k0 + j <= qi) ? s_ : -INFINITY;
        }

        float mnew = m;
#pragma unroll
        for (int j = 0; j < TK; j++) mnew = fmaxf(mnew, sc[j]);
        float scale = __expf(m - mnew);
        m = mnew;
        l *= scale;
#pragma unroll
        for (int d = 0; d < HD; d++) acc[d] *= scale;

#pragma unroll
        for (int j = 0; j < TK; j++) {
            float p = __expf(sc[j] - mnew);
            l += p;
#pragma unroll
            for (int d = 0; d < HD; d++) acc[d] += p * Vsh[j][d];
        }
        __syncthreads();
    }

    float inv_l = 1.0f / l;
    float* o = g_att + (size_t)row * DD + h * HD;
#pragma unroll
    for (int d = 0; d < HD; d++) o[d] = acc[d] * inv_l;
}

// ---------------------------------------------------------------------------
// Launch
// Inputs (metadata order): 0=inputs f32[B,S,D], 1=segment_positions i32[B,S],
// 2=mask bool (unused; causal), 3=W_in f32[D,3D], 4=W_out f32[D,D].
// Output: f32[B,S,D].
// ---------------------------------------------------------------------------
extern "C" void kernel_launch(void* const* d_in, const int* in_sizes, int n_in,
                              void* d_out, int out_size)
{
    const float* x    = (const float*)d_in[0];
    const int*   pos  = (const int*)d_in[1];
    const float* Win  = (const float*)d_in[3];
    const float* Wout = (const float*)d_in[4];
    float* out = (float*)d_out;

    float *qkv, *att;
    cudaGetSymbolAddress((void**)&qkv, g_qkv);
    cudaGetSymbolAddress((void**)&att, g_att);

    // 1) QKV projection: [4096,1024] @ [1024,3072]
    dim3 g1(3 * DD / 128, ROWS / 128);   // (24, 32)
    sgemm_k<<<g1, 256>>>(x, Win, qkv, ROWS, 3 * DD, DD);

    // 2) RoPE + q-scaling in-place
    int nrope = ROWS * HH * 2 * 32;
    rope_k<<<(nrope + 255) / 256, 256>>>(pos);

    // 3) Causal flash attention
    flash_k<<<dim3(SS / TQ, BB * HH), 128>>>();

    // 4) Output projection: [4096,1024] @ [1024,1024]
    dim3 g2(DD / 128, ROWS / 128);       // (8, 32)
    sgemm_k<<<g2, 256>>>(att, Wout, out, ROWS, DD, DD);
}

// round 2
// speedup vs baseline: 1.1301x; 1.1301x over previous
#include <cuda_runtime.h>
#include <math.h>

#define BB 2
#define SS 2048
#define DD 1024
#define HH 16
#define HD 64
#define ROWS (BB*SS)      // 4096
#define TRIPLE (3*HD)     // 192 floats per (row, head)

// Scratch (static device globals; no allocation at runtime)
__device__ float g_qkv[(size_t)ROWS * 3 * DD];   // [ROWS][H][192]
__device__ float g_att[(size_t)ROWS * DD];       // [ROWS][H][64]

// ---------------------------------------------------------------------------
// SGEMM v2: C[M,N] = A[M,K] @ B[K,N], fp32, 128x128 tile, BK=16, 256 threads,
// 8x8 register blocking, double-buffered smem with register prefetch.
// ---------------------------------------------------------------------------
__global__ __launch_bounds__(256) void sgemm_k(const float* __restrict__ A,
                                               const float* __restrict__ Bm,
                                               float* __restrict__ C,
                                               int M, int N, int K)
{
    __shared__ float As[2][16][128];
    __shared__ float Bs[2][16][128];
    const int tid = threadIdx.x;
    const int tx = tid & 15;        // N direction (8 cols each)
    const int ty = tid >> 4;        // M direction (8 rows each)
    const float* Ag = A + (size_t)blockIdx.y * 128 * K;
    const float* Bg = Bm + (size_t)blockIdx.x * 128;

    // Global-load assignment: each thread fetches 2 adjacent float4 of A and B
    const int rA = tid >> 1;             // A row   0..127
    const int cA = (tid & 1) * 8;        // A col   0 or 8
    const int rB = tid >> 4;             // B row   0..15
    const int cB = (tid & 15) * 8;       // B col   0..120 step 8

    float acc[8][8];
#pragma unroll
    for (int i = 0; i < 8; i++)
#pragma unroll
        for (int j = 0; j < 8; j++) acc[i][j] = 0.f;

    float4 a0, a1, b0, b1;

    // prologue: fetch + stage tile 0
    {
        const float* ap = Ag + (size_t)rA * K + cA;
        a0 = *(const float4*)ap; a1 = *(const float4*)(ap + 4);
        const float* bp = Bg + (size_t)rB * N + cB;
        b0 = *(const float4*)bp; b1 = *(const float4*)(bp + 4);
        As[0][cA + 0][rA] = a0.x; As[0][cA + 1][rA] = a0.y;
        As[0][cA + 2][rA] = a0.z; As[0][cA + 3][rA] = a0.w;
        As[0][cA + 4][rA] = a1.x; As[0][cA + 5][rA] = a1.y;
        As[0][cA + 6][rA] = a1.z; As[0][cA + 7][rA] = a1.w;
        *(float4*)&Bs[0][rB][cB] = b0;
        *(float4*)&Bs[0][rB][cB + 4] = b1;
    }
    __syncthreads();

    const int nk = K >> 4;
    for (int kt = 0; kt < nk; kt++) {
        const int cur = kt & 1;
        if (kt + 1 < nk) {
            const int k0 = (kt + 1) * 16;
            const float* ap = Ag + (size_t)rA * K + k0 + cA;
            a0 = *(const float4*)ap; a1 = *(const float4*)(ap + 4);
            const float* bp = Bg + (size_t)(k0 + rB) * N + cB;
            b0 = *(const float4*)bp; b1 = *(const float4*)(bp + 4);
        }
#pragma unroll
        for (int kk = 0; kk < 16; kk++) {
            float ra[8], rb[8];
            *(float4*)(ra)     = *(const float4*)&As[cur][kk][ty * 8];
            *(float4*)(ra + 4) = *(const float4*)&As[cur][kk][ty * 8 + 4];
            *(float4*)(rb)     = *(const float4*)&Bs[cur][kk][tx * 8];
            *(float4*)(rb + 4) = *(const float4*)&Bs[cur][kk][tx * 8 + 4];
#pragma unroll
            for (int i = 0; i < 8; i++)
#pragma unroll
                for (int j = 0; j < 8; j++) acc[i][j] += ra[i] * rb[j];
        }
        if (kt + 1 < nk) {
            const int nxt = cur ^ 1;
            As[nxt][cA + 0][rA] = a0.x; As[nxt][cA + 1][rA] = a0.y;
            As[nxt][cA + 2][rA] = a0.z; As[nxt][cA + 3][rA] = a0.w;
            As[nxt][cA + 4][rA] = a1.x; As[nxt][cA + 5][rA] = a1.y;
            As[nxt][cA + 6][rA] = a1.z; As[nxt][cA + 7][rA] = a1.w;
            *(float4*)&Bs[nxt][rB][cB] = b0;
            *(float4*)&Bs[nxt][rB][cB + 4] = b1;
            __syncthreads();
        }
    }

    float* Cg = C + (size_t)(blockIdx.y * 128 + ty * 8) * N + blockIdx.x * 128 + tx * 8;
#pragma unroll
    for (int i = 0; i < 8; i++) {
#pragma unroll
        for (int j = 0; j < 8; j += 4) {
            float4 v = make_float4(acc[i][j], acc[i][j + 1], acc[i][j + 2], acc[i][j + 3]);
            *(float4*)(Cg + (size_t)i * N + j) = v;
        }
    }
}

// ---------------------------------------------------------------------------
// RoPE (rotate-half, base 10000) in-place on q,k of g_qkv; scales q by 0.125.
// ---------------------------------------------------------------------------
__global__ void rope_k(const int* __restrict__ pos)
{
    int idx = blockIdx.x * blockDim.x + threadIdx.x;
    const int total = ROWS * HH * 2 * 32;
    if (idx >= total) return;
    int i = idx & 31;
    int rest = idx >> 5;
    int comp = rest & 1; rest >>= 1;   // 0 = q, 1 = k
    int h = rest & 15;
    int row = rest >> 4;

    float p = (float)pos[row];
    float inv = powf(10000.0f, -(float)i * (1.0f / 32.0f));
    float ang = p * inv;
    float sn, cs;
    sincosf(ang, &sn, &cs);

    float* base = g_qkv + ((size_t)row * HH + h) * TRIPLE + comp * HD;
    float x1 = base[i];
    float x2 = base[i + 32];
    float o1 = x1 * cs - x2 * sn;
    float o2 = x1 * sn + x2 * cs;
    if (comp == 0) { o1 *= 0.125f; o2 *= 0.125f; }
    base[i] = o1;
    base[i + 32] = o2;
}

// ---------------------------------------------------------------------------
// Causal flash attention v2, fp32.
// grid = (S/128, B*H), 128 threads (4 warps).
// Lane layout: dsl = lane&3 owns a 16-float slice of head_dim;
//              qsub = lane>>2; each thread owns 4 queries (register q/acc).
// Scores all-reduced over the 4 slice-lanes with shfl.bfly (1,2).
// ---------------------------------------------------------------------------
#define TQF 128
#define TKF 32
__global__ __launch_bounds__(128) void flash_k()
{
    __shared__ float Ksh[TKF][HD];   // 8 KB
    __shared__ float Vsh[TKF][HD];   // 8 KB
    const int t = threadIdx.x;
    const int lane = t & 31;
    const int w = t >> 5;
    const int dsl = lane & 3;
    const int d0 = dsl * 16;
    const int qsub = lane >> 2;      // 0..7
    const int b = blockIdx.y >> 4;
    const int h = blockIdx.y & 15;
    const int qstart = blockIdx.x * TQF;
    const int qbase = qstart + w * 32 + qsub * 4;   // first of 4 queries

    float q[4][16], acc[4][16], m[4], l[4];
#pragma unroll
    for (int g = 0; g < 4; g++) {
        const float* qp = g_qkv + ((size_t)(b * SS + qbase + g) * HH + h) * TRIPLE + d0;
#pragma unroll
        for (int ii = 0; ii < 16; ii += 4) {
            float4 v = *(const float4*)(qp + ii);
            q[g][ii] = v.x; q[g][ii + 1] = v.y; q[g][ii + 2] = v.z; q[g][ii + 3] = v.w;
        }
        m[g] = -INFINITY; l[g] = 0.f;
#pragma unroll
        for (int ii = 0; ii < 16; ii++) acc[g][ii] = 0.f;
    }

    const int ntiles = (qstart + TQF) / TKF;
    for (int tt = 0; tt < ntiles; tt++) {
        const int k0 = tt * TKF;
        // cooperative K/V tile load: 32 rows x 64 floats each
#pragma unroll
        for (int uu = 0; uu < 4; uu++) {
            int u = t + uu * 128;
            int j = u >> 4;
            int c = (u & 15) * 4;
            const float* kvb = g_qkv + ((size_t)(b * SS + k0 + j) * HH + h) * TRIPLE;
            *(float4*)&Ksh[j][c] = *(const float4*)(kvb + HD + c);
            *(float4*)&Vsh[j][c] = *(const float4*)(kvb + 2 * HD + c);
        }
        __syncthreads();

        for (int jc = 0; jc < TKF; jc += 8) {
            float sc[8][4];
#pragma unroll
            for (int jj = 0; jj < 8; jj++) {
                const int j = jc + jj;
                float kv[16];
#pragma unroll
                for (int ii = 0; ii < 16; ii += 4)
                    *(float4*)&kv[ii] = *(const float4*)&Ksh[j][d0 + ii];
                float s0 = 0.f, s1 = 0.f, s2 = 0.f, s3 = 0.f;
#pragma unroll
                for (int ii = 0; ii < 16; ii++) {
                    s0 += q[0][ii] * kv[ii];
                    s1 += q[1][ii] * kv[ii];
                    s2 += q[2][ii] * kv[ii];
                    s3 += q[3][ii] * kv[ii];
                }
                s0 += __shfl_xor_sync(0xffffffffu, s0, 1);
                s0 += __shfl_xor_sync(0xffffffffu, s0, 2);
                s1 += __shfl_xor_sync(0xffffffffu, s1, 1);
                s1 += __shfl_xor_sync(0xffffffffu, s1, 2);
                s2 += __shfl_xor_sync(0xffffffffu, s2, 1);
                s2 += __shfl_xor_sync(0xffffffffu, s2, 2);
                s3 += __shfl_xor_sync(0xffffffffu, s3, 1);
                s3 += __shfl_xor_sync(0xffffffffu, s3, 2);
                const int kidx = k0 + j;
                sc[jj][0] = (kidx <= qbase + 0) ? s0 : -INFINITY;
                sc[jj][1] = (kidx <= qbase + 1) ? s1 : -INFINITY;
                sc[jj][2] = (kidx <= qbase + 2) ? s2 : -INFINITY;
                sc[jj][3] = (kidx <= qbase + 3) ? s3 : -INFINITY;
            }
            // online softmax update (state replicated across the 4 slice-lanes)
#pragma unroll
            for (int g = 0; g < 4; g++) {
                float mc = sc[0][g];
#pragma unroll
                for (int jj = 1; jj < 8; jj++) mc = fmaxf(mc, sc[jj][g]);
                float mn = fmaxf(m[g], mc);
                float ls = 0.f;
#pragma unroll
                for (int jj = 0; jj < 8; jj++) {
                    float p = __expf(sc[jj][g] - mn);
                    sc[jj][g] = p;
                    ls += p;
                }
                float scale = __expf(m[g] - mn);
                m[g] = mn;
                l[g] = l[g] * scale + ls;
                if (scale != 1.f) {
#pragma unroll
                    for (int ii = 0; ii < 16; ii++) acc[g][ii] *= scale;
                }
            }
            // P @ V
#pragma unroll
            for (int jj = 0; jj < 8; jj++) {
                const int j = jc + jj;
                float vv[16];
#pragma unroll
                for (int ii = 0; ii < 16; ii += 4)
                    *(float4*)&vv[ii] = *(const float4*)&Vsh[j][d0 + ii];
#pragma unroll
                for (int ii = 0; ii < 16; ii++) {
                    acc[0][ii] += sc[jj][0] * vv[ii];
                    acc[1][ii] += sc[jj][1] * vv[ii];
                    acc[2][ii] += sc[jj][2] * vv[ii];
                    acc[3][ii] += sc[jj][3] * vv[ii];
                }
            }
        }
        __syncthreads();
    }

#pragma unroll
    for (int g = 0; g < 4; g++) {
        float invl = 1.0f / l[g];
        float* o = g_att + (size_t)(b * SS + qbase + g) * DD + h * HD + d0;
#pragma unroll
        for (int ii = 0; ii < 16; ii += 4) {
            float4 v = make_float4(acc[g][ii] * invl, acc[g][ii + 1] * invl,
                                   acc[g][ii + 2] * invl, acc[g][ii + 3] * invl);
            *(float4*)(o + ii) = v;
        }
    }
}

// ---------------------------------------------------------------------------
// Launch
// Inputs: 0=inputs f32[B,S,D], 1=segment_positions i32[B,S], 2=mask (unused),
// 3=W_in f32[D,3D], 4=W_out f32[D,D]. Output: f32[B,S,D].
// ---------------------------------------------------------------------------
extern "C" void kernel_launch(void* const* d_in, const int* in_sizes, int n_in,
                              void* d_out, int out_size)
{
    const float* x    = (const float*)d_in[0];
    const int*   pos  = (const int*)d_in[1];
    const float* Win  = (const float*)d_in[3];
    const float* Wout = (const float*)d_in[4];
    float* out = (float*)d_out;

    float *qkv, *att;
    cudaGetSymbolAddress((void**)&qkv, g_qkv);
    cudaGetSymbolAddress((void**)&att, g_att);

    // 1) QKV projection: [4096,1024] @ [1024,3072]
    dim3 g1(3 * DD / 128, ROWS / 128);   // (24, 32)
    sgemm_k<<<g1, 256>>>(x, Win, qkv, ROWS, 3 * DD, DD);

    // 2) RoPE + q-scaling in-place
    int nrope = ROWS * HH * 2 * 32;
    rope_k<<<(nrope + 255) / 256, 256>>>(pos);

    // 3) Causal flash attention v2
    flash_k<<<dim3(SS / TQF, BB * HH), 128>>>();

    // 4) Output projection: [4096,1024] @ [1024,1024]
    dim3 g2(DD / 128, ROWS / 128);       // (8, 32)
    sgemm_k<<<g2, 256>>>(att, Wout, out, ROWS, DD, DD);
}

// round 4
// speedup vs baseline: 1.5666x; 1.3862x over previous
#include <cuda_runtime.h>
#include <cuda_bf16.h>
#include <math.h>
#include <stdint.h>

#define BB 2
#define SS 2048
#define DD 1024
#define HH 16
#define HD 64
#define ROWS (BB*SS)      // 4096
#define TRIPLE (3*HD)     // 192 floats per (row, head)
#define GK 1024           // GEMM K dim (fixed)

// ---------------------------------------------------------------------------
// Scratch (static device globals; no allocation at runtime)
// ---------------------------------------------------------------------------
__device__ float g_qkv[(size_t)ROWS * 3 * DD];        // [ROWS][H][192] fp32
__device__ float g_att[(size_t)ROWS * DD];            // [ROWS][H][64]  fp32
__device__ __nv_bfloat16 g_ahi[(size_t)ROWS * DD];    // inputs split hi [row][K]
__device__ __nv_bfloat16 g_alo[(size_t)ROWS * DD];    // inputs split lo
__device__ __nv_bfloat16 g_chi[(size_t)ROWS * DD];    // att split hi
__device__ __nv_bfloat16 g_clo[(size_t)ROWS * DD];    // att split lo
__device__ __nv_bfloat16 g_whiT[(size_t)3 * DD * DD]; // W_in^T hi [3072][1024]
__device__ __nv_bfloat16 g_wloT[(size_t)3 * DD * DD]; // W_in^T lo
__device__ __nv_bfloat16 g_ohiT[(size_t)DD * DD];     // W_out^T hi [1024][1024]
__device__ __nv_bfloat16 g_oloT[(size_t)DD * DD];     // W_out^T lo

// ---------------------------------------------------------------------------
// PTX helpers (portable: mma.sync / ldmatrix / cp.async — no arch-'a' features)
// ---------------------------------------------------------------------------
__device__ __forceinline__ uint32_t smem_to_u32(const void* smem_ptr) {
    uint32_t addr;
    asm("{ .reg .u64 tmp; cvta.to.shared.u64 tmp, %1; cvt.u32.u64 %0, tmp; }"
        : "=r"(addr) : "l"(smem_ptr));
    return addr;
}
__device__ __forceinline__ void ldsm4(uint32_t* r, uint32_t addr) {
    asm volatile("ldmatrix.sync.aligned.m8n8.x4.shared.b16 {%0,%1,%2,%3}, [%4];"
                 : "=r"(r[0]), "=r"(r[1]), "=r"(r[2]), "=r"(r[3]) : "r"(addr));
}
__device__ __forceinline__ void mma16816(float* c, const uint32_t* a, const uint32_t* b) {
    asm volatile(
        "mma.sync.aligned.m16n8k16.row.col.f32.bf16.bf16.f32 "
        "{%0,%1,%2,%3}, {%4,%5,%6,%7}, {%8,%9}, {%0,%1,%2,%3};"
        : "+f"(c[0]), "+f"(c[1]), "+f"(c[2]), "+f"(c[3])
        : "r"(a[0]), "r"(a[1]), "r"(a[2]), "r"(a[3]), "r"(b[0]), "r"(b[1]));
}
#define CP_ASYNC16(sm_u32, gptr) \
    asm volatile("cp.async.cg.shared.global [%0], [%1], 16;" :: "r"(sm_u32), "l"(gptr))
#define CP_COMMIT() asm volatile("cp.async.commit_group;" ::: "memory")
#define CP_WAIT1()  asm volatile("cp.async.wait_group 1;" ::: "memory")
#define CP_WAIT0()  asm volatile("cp.async.wait_group 0;" ::: "memory")

// ---------------------------------------------------------------------------
// Split/convert kernels
// ---------------------------------------------------------------------------
__global__ void split_k(const float* __restrict__ in,
                        __nv_bfloat16* __restrict__ hi,
                        __nv_bfloat16* __restrict__ lo, int n)
{
    int i = blockIdx.x * blockDim.x + threadIdx.x;
    if (i >= n) return;
    float v = in[i];
    __nv_bfloat16 h = __float2bfloat16_rn(v);
    hi[i] = h;
    lo[i] = __float2bfloat16_rn(v - __bfloat162float(h));
}

// Transpose + split: in [K][N] fp32 -> hiT/loT [N][K] bf16
__global__ __launch_bounds__(256) void tsplit_k(const float* __restrict__ in,
                                                __nv_bfloat16* __restrict__ hiT,
                                                __nv_bfloat16* __restrict__ loT,
                                                int K, int N)
{
    __shared__ float tile[32][33];
    const int tx = threadIdx.x & 31;
    const int ty = threadIdx.x >> 5;       // 0..7
    const int n0 = blockIdx.x * 32;
    const int k0 = blockIdx.y * 32;
#pragma unroll
    for (int i = 0; i < 4; i++) {
        int kk = ty + 8 * i;
        tile[kk][tx] = in[(size_t)(k0 + kk) * N + n0 + tx];
    }
    __syncthreads();
#pragma unroll
    for (int i = 0; i < 4; i++) {
        int nn = ty + 8 * i;
        float v = tile[tx][nn];
        __nv_bfloat16 h = __float2bfloat16_rn(v);
        size_t o = (size_t)(n0 + nn) * K + k0 + tx;
        hiT[o] = h;
        loT[o] = __float2bfloat16_rn(v - __bfloat162float(h));
    }
}

// ---------------------------------------------------------------------------
// HMMA bf16-split GEMM: C[M,N] = (Ahi+Alo)[M,K] * (Bhi+Blo)^T  (B given [N][K])
// 128x128 block, 8 warps (warp tile 64x32), KC=32, cp.async 2-stage pipeline.
// smem tiles row-padded to 80B (conflict-free ldmatrix).
// ---------------------------------------------------------------------------
#define KC 32
#define NKC (GK / KC)            // 32
#define ROWB 80                  // 32 bf16 = 64B data + 16B pad
#define TILE_SB (128 * ROWB)     // 10240
#define STAGE_SB (4 * TILE_SB)   // Ahi, Alo, Bhi, Blo = 40960
#define GEMM_SMEM_SZ (2 * STAGE_SB)  // 81920

__global__ __launch_bounds__(256) void gemm_hmma_k(
    const __nv_bfloat16* __restrict__ ahi, const __nv_bfloat16* __restrict__ alo,
    const __nv_bfloat16* __restrict__ bhiT, const __nv_bfloat16* __restrict__ bloT,
    float* __restrict__ C, int N)
{
    extern __shared__ char sm[];
    const uint32_t sb = smem_to_u32(sm);
    const int t = threadIdx.x;
    const int lane = t & 31;
    const int wid = t >> 5;
    const int wm = wid & 1;          // 2 m-blocks of 64
    const int wn = wid >> 1;         // 4 n-blocks of 32
    const size_t arow0 = (size_t)blockIdx.y * 128;
    const size_t brow0 = (size_t)blockIdx.x * 128;

    const __nv_bfloat16* gsrc[4] = {
        ahi + arow0 * GK, alo + arow0 * GK,
        bhiT + brow0 * GK, bloT + brow0 * GK };

    // stage loader: 4 tiles x 128 rows x 64B, 16B per cp.async
    auto issue_stage = [&](int c) {
        const uint32_t st = sb + (c & 1) * STAGE_SB;
        const size_t k0 = (size_t)c * KC;
#pragma unroll
        for (int comp = 0; comp < 4; comp++) {
#pragma unroll
            for (int i = 0; i < 2; i++) {
                int u = t + i * 256;
                int r = u >> 2, ch = u & 3;
                const void* g = gsrc[comp] + (size_t)r * GK + k0 + ch * 8;
                CP_ASYNC16(st + comp * TILE_SB + r * ROWB + ch * 16, g);
            }
        }
        CP_COMMIT();
    };

    float acc[4][4][4];
#pragma unroll
    for (int mt = 0; mt < 4; mt++)
#pragma unroll
        for (int nt = 0; nt < 4; nt++)
#pragma unroll
            for (int i = 0; i < 4; i++) acc[mt][nt][i] = 0.f;

    issue_stage(0);
    issue_stage(1);

    const int idx = lane & 7;
    const int sel = lane >> 3;

    for (int c = 0; c < NKC; c++) {
        if (c + 1 < NKC) { CP_WAIT1(); } else { CP_WAIT0(); }
        __syncthreads();
        const uint32_t st = sb + (c & 1) * STAGE_SB;

#pragma unroll
        for (int j = 0; j < 2; j++) {       // two k16 steps per KC
            uint32_t ahif[4][4], alof[4][4], bhif[4][2], blof[4][2];
            // A fragments: rows wm*64 + mt*16 + (sel&1)*8 + idx, chunk 2j + (sel>>1)
            const uint32_t acol = (uint32_t)((2 * j + (sel >> 1)) << 4);
#pragma unroll
            for (int mt = 0; mt < 4; mt++) {
                uint32_t ra = (uint32_t)(wm * 64 + mt * 16 + ((sel & 1) << 3) + idx);
                uint32_t ad = st + ra * ROWB + acol;
                ldsm4(ahif[mt], ad);
                ldsm4(alof[mt], ad + TILE_SB);
            }
            // B fragments: rows wn*32 + (sel>>1)*8 + idx, chunk 2j + (sel&1)
            {
                const uint32_t bcol = (uint32_t)((2 * j + (sel & 1)) << 4);
                uint32_t rb = (uint32_t)(wn * 32 + ((sel >> 1) << 3) + idx);
                uint32_t bd = st + 2 * TILE_SB + rb * ROWB + bcol;
                uint32_t tmp[4];
                ldsm4(tmp, bd);                    // n tiles 0,1 (hi)
                bhif[0][0] = tmp[0]; bhif[0][1] = tmp[1];
                bhif[1][0] = tmp[2]; bhif[1][1] = tmp[3];
                ldsm4(tmp, bd + 16 * ROWB);        // n tiles 2,3 (hi)
                bhif[2][0] = tmp[0]; bhif[2][1] = tmp[1];
                bhif[3][0] = tmp[2]; bhif[3][1] = tmp[3];
                ldsm4(tmp, bd + TILE_SB);          // n tiles 0,1 (lo)
                blof[0][0] = tmp[0]; blof[0][1] = tmp[1];
                blof[1][0] = tmp[2]; blof[1][1] = tmp[3];
                ldsm4(tmp, bd + TILE_SB + 16 * ROWB);
                blof[2][0] = tmp[0]; blof[2][1] = tmp[1];
                blof[3][0] = tmp[2]; blof[3][1] = tmp[3];
            }
#pragma unroll
            for (int mt = 0; mt < 4; mt++)
#pragma unroll
                for (int nt = 0; nt < 4; nt++) {
                    mma16816(acc[mt][nt], ahif[mt], bhif[nt]);
                    mma16816(acc[mt][nt], ahif[mt], blof[nt]);
                    mma16816(acc[mt][nt], alof[mt], bhif[nt]);
                }
        }
        __syncthreads();
        if (c + 2 < NKC) issue_stage(c + 2);
    }

    // epilogue: c0,c1 -> (row g, col tg*2), c2,c3 -> (row g+8)
    const int g = lane >> 2, tg = lane & 3;
#pragma unroll
    for (int mt = 0; mt < 4; mt++) {
        size_t row0 = arow0 + wm * 64 + mt * 16 + g;
#pragma unroll
        for (int nt = 0; nt < 4; nt++) {
            size_t col = brow0 + wn * 32 + nt * 8 + tg * 2;
            *(float2*)(C + row0 * N + col) = make_float2(acc[mt][nt][0], acc[mt][nt][1]);
            *(float2*)(C + (row0 + 8) * N + col) = make_float2(acc[mt][nt][2], acc[mt][nt][3]);
        }
    }
}

// ---------------------------------------------------------------------------
// RoPE (rotate-half, base 10000) in-place on q,k of g_qkv; scales q by 0.125.
// ---------------------------------------------------------------------------
__global__ void rope_k(const int* __restrict__ pos)
{
    int idx = blockIdx.x * blockDim.x + threadIdx.x;
    const int total = ROWS * HH * 2 * 32;
    if (idx >= total) return;
    int i = idx & 31;
    int rest = idx >> 5;
    int comp = rest & 1; rest >>= 1;   // 0 = q, 1 = k
    int h = rest & 15;
    int row = rest >> 4;

    float p = (float)pos[row];
    float inv = powf(10000.0f, -(float)i * (1.0f / 32.0f));
    float ang = p * inv;
    float sn, cs;
    sincosf(ang, &sn, &cs);

    float* base = g_qkv + ((size_t)row * HH + h) * TRIPLE + comp * HD;
    float x1 = base[i];
    float x2 = base[i + 32];
    float o1 = x1 * cs - x2 * sn;
    float o2 = x1 * sn + x2 * cs;
    if (comp == 0) { o1 *= 0.125f; o2 *= 0.125f; }
    base[i] = o1;
    base[i + 32] = o2;
}

// ---------------------------------------------------------------------------
// Causal flash attention v2 (fp32 SIMT) — unchanged (passing, ~860us; next target).
// ---------------------------------------------------------------------------
#define TQF 128
#define TKF 32
__global__ __launch_bounds__(128) void flash_k()
{
    __shared__ float Ksh[TKF][HD];
    __shared__ float Vsh[TKF][HD];
    const int t = threadIdx.x;
    const int lane = t & 31;
    const int w = t >> 5;
    const int dsl = lane & 3;
    const int d0 = dsl * 16;
    const int qsub = lane >> 2;
    const int b = blockIdx.y >> 4;
    const int h = blockIdx.y & 15;
    const int qstart = blockIdx.x * TQF;
    const int qbase = qstart + w * 32 + qsub * 4;

    float q[4][16], acc[4][16], m[4], l[4];
#pragma unroll
    for (int g = 0; g < 4; g++) {
        const float* qp = g_qkv + ((size_t)(b * SS + qbase + g) * HH + h) * TRIPLE + d0;
#pragma unroll
        for (int ii = 0; ii < 16; ii += 4) {
            float4 v = *(const float4*)(qp + ii);
            q[g][ii] = v.x; q[g][ii + 1] = v.y; q[g][ii + 2] = v.z; q[g][ii + 3] = v.w;
        }
        m[g] = -INFINITY; l[g] = 0.f;
#pragma unroll
        for (int ii = 0; ii < 16; ii++) acc[g][ii] = 0.f;
    }

    const int ntiles = (qstart + TQF) / TKF;
    for (int tt = 0; tt < ntiles; tt++) {
        const int k0 = tt * TKF;
#pragma unroll
        for (int uu = 0; uu < 4; uu++) {
            int u = t + uu * 128;
            int j = u >> 4;
            int c = (u & 15) * 4;
            const float* kvb = g_qkv + ((size_t)(b * SS + k0 + j) * HH + h) * TRIPLE;
            *(float4*)&Ksh[j][c] = *(const float4*)(kvb + HD + c);
            *(float4*)&Vsh[j][c] = *(const float4*)(kvb + 2 * HD + c);
        }
        __syncthreads();

        for (int jc = 0; jc < TKF; jc += 8) {
            float sc[8][4];
#pragma unroll
            for (int jj = 0; jj < 8; jj++) {
                const int j = jc + jj;
                float kv[16];
#pragma unroll
                for (int ii = 0; ii < 16; ii += 4)
                    *(float4*)&kv[ii] = *(const float4*)&Ksh[j][d0 + ii];
                float s0 = 0.f, s1 = 0.f, s2 = 0.f, s3 = 0.f;
#pragma unroll
                for (int ii = 0; ii < 16; ii++) {
                    s0 += q[0][ii] * kv[ii];
                    s1 += q[1][ii] * kv[ii];
                    s2 += q[2][ii] * kv[ii];
                    s3 += q[3][ii] * kv[ii];
                }
                s0 += __shfl_xor_sync(0xffffffffu, s0, 1);
                s0 += __shfl_xor_sync(0xffffffffu, s0, 2);
                s1 += __shfl_xor_sync(0xffffffffu, s1, 1);
                s1 += __shfl_xor_sync(0xffffffffu, s1, 2);
                s2 += __shfl_xor_sync(0xffffffffu, s2, 1);
                s2 += __shfl_xor_sync(0xffffffffu, s2, 2);
                s3 += __shfl_xor_sync(0xffffffffu, s3, 1);
                s3 += __shfl_xor_sync(0xffffffffu, s3, 2);
                const int kidx = k0 + j;
                sc[jj][0] = (kidx <= qbase + 0) ? s0 : -INFINITY;
                sc[jj][1] = (kidx <= qbase + 1) ? s1 : -INFINITY;
                sc[jj][2] = (kidx <= qbase + 2) ? s2 : -INFINITY;
                sc[jj][3] = (kidx <= qbase + 3) ? s3 : -INFINITY;
            }
#pragma unroll
            for (int g = 0; g < 4; g++) {
                float mc = sc[0][g];
#pragma unroll
                for (int jj = 1; jj < 8; jj++) mc = fmaxf(mc, sc[jj][g]);
                float mn = fmaxf(m[g], mc);
                float ls = 0.f;
#pragma unroll
                for (int jj = 0; jj < 8; jj++) {
                    float p = __expf(sc[jj][g] - mn);
                    sc[jj][g] = p;
                    ls += p;
                }
                float scale = __expf(m[g] - mn);
                m[g] = mn;
                l[g] = l[g] * scale + ls;
                if (scale != 1.f) {
#pragma unroll
                    for (int ii = 0; ii < 16; ii++) acc[g][ii] *= scale;
                }
            }
#pragma unroll
            for (int jj = 0; jj < 8; jj++) {
                const int j = jc + jj;
                float vv[16];
#pragma unroll
                for (int ii = 0; ii < 16; ii += 4)
                    *(float4*)&vv[ii] = *(const float4*)&Vsh[j][d0 + ii];
#pragma unroll
                for (int ii = 0; ii < 16; ii++) {
                    acc[0][ii] += sc[jj][0] * vv[ii];
                    acc[1][ii] += sc[jj][1] * vv[ii];
                    acc[2][ii] += sc[jj][2] * vv[ii];
                    acc[3][ii] += sc[jj][3] * vv[ii];
                }
            }
        }
        __syncthreads();
    }

#pragma unroll
    for (int g = 0; g < 4; g++) {
        float invl = 1.0f / l[g];
        float* o = g_att + (size_t)(b * SS + qbase + g) * DD + h * HD + d0;
#pragma unroll
        for (int ii = 0; ii < 16; ii += 4) {
            float4 v = make_float4(acc[g][ii] * invl, acc[g][ii + 1] * invl,
                                   acc[g][ii + 2] * invl, acc[g][ii + 3] * invl);
            *(float4*)(o + ii) = v;
        }
    }
}

// ---------------------------------------------------------------------------
// Launch
// Inputs: 0=inputs f32[B,S,D], 1=segment_positions i32[B,S], 2=mask (unused),
// 3=W_in f32[D,3D], 4=W_out f32[D,D]. Output: f32[B,S,D].
// ---------------------------------------------------------------------------
extern "C" void kernel_launch(void* const* d_in, const int* in_sizes, int n_in,
                              void* d_out, int out_size)
{
    const float* x    = (const float*)d_in[0];
    const int*   pos  = (const int*)d_in[1];
    const float* Win  = (const float*)d_in[3];
    const float* Wout = (const float*)d_in[4];
    float* out = (float*)d_out;

    float *qkv, *att;
    __nv_bfloat16 *ahi, *alo, *chi, *clo, *whiT, *wloT, *ohiT, *oloT;
    cudaGetSymbolAddress((void**)&qkv, g_qkv);
    cudaGetSymbolAddress((void**)&att, g_att);
    cudaGetSymbolAddress((void**)&ahi, g_ahi);
    cudaGetSymbolAddress((void**)&alo, g_alo);
    cudaGetSymbolAddress((void**)&chi, g_chi);
    cudaGetSymbolAddress((void**)&clo, g_clo);
    cudaGetSymbolAddress((void**)&whiT, g_whiT);
    cudaGetSymbolAddress((void**)&wloT, g_wloT);
    cudaGetSymbolAddress((void**)&ohiT, g_ohiT);
    cudaGetSymbolAddress((void**)&oloT, g_oloT);

    cudaFuncSetAttribute(gemm_hmma_k,
                         cudaFuncAttributeMaxDynamicSharedMemorySize, GEMM_SMEM_SZ);

    // 0) split inputs, transpose+split weights
    {
        int n = ROWS * DD;
        split_k<<<(n + 255) / 256, 256>>>(x, ahi, alo, n);
    }
    tsplit_k<<<dim3(3 * DD / 32, DD / 32), 256>>>(Win, whiT, wloT, DD, 3 * DD);
    tsplit_k<<<dim3(DD / 32, DD / 32), 256>>>(Wout, ohiT, oloT, DD, DD);

    // 1) QKV projection via HMMA: [4096,1024] x [1024,3072]
    gemm_hmma_k<<<dim3(3 * DD / 128, ROWS / 128), 256, GEMM_SMEM_SZ>>>(
        ahi, alo, whiT, wloT, qkv, 3 * DD);

    // 2) RoPE + q-scaling in-place
    int nrope = ROWS * HH * 2 * 32;
    rope_k<<<(nrope + 255) / 256, 256>>>(pos);

    // 3) Causal flash attention (fp32 SIMT)
    flash_k<<<dim3(SS / TQF, BB * HH), 128>>>();

    // 4) split attention output, then output projection via HMMA
    {
        int n = ROWS * DD;
        split_k<<<(n + 255) / 256, 256>>>(att, chi, clo, n);
    }
    gemm_hmma_k<<<dim3(DD / 128, ROWS / 128), 256, GEMM_SMEM_SZ>>>(
        chi, clo, ohiT, oloT, out, DD);
}

// round 5
// speedup vs baseline: 3.5426x; 2.2614x over previous
#include <cuda_runtime.h>
#include <cuda_bf16.h>
#include <math.h>
#include <stdint.h>

#define BB 2
#define SS 2048
#define DD 1024
#define HH 16
#define HD 64
#define ROWS (BB*SS)      // 4096
#define TRIPLE (3*HD)     // 192 floats per (row, head)
#define GK 1024           // GEMM K dim (fixed)

// ---------------------------------------------------------------------------
// Scratch (static device globals; no allocation at runtime)
// ---------------------------------------------------------------------------
__device__ float g_qkv[(size_t)ROWS * 3 * DD];        // [ROWS][H][192] fp32
__device__ __nv_bfloat16 g_ahi[(size_t)ROWS * DD];    // inputs split hi [row][K]
__device__ __nv_bfloat16 g_alo[(size_t)ROWS * DD];    // inputs split lo
__device__ __nv_bfloat16 g_chi[(size_t)ROWS * DD];    // attn out split hi [row][D]
__device__ __nv_bfloat16 g_clo[(size_t)ROWS * DD];    // attn out split lo
__device__ __nv_bfloat16 g_whiT[(size_t)3 * DD * DD]; // W_in^T hi [3072][1024]
__device__ __nv_bfloat16 g_wloT[(size_t)3 * DD * DD]; // W_in^T lo
__device__ __nv_bfloat16 g_ohiT[(size_t)DD * DD];     // W_out^T hi [1024][1024]
__device__ __nv_bfloat16 g_oloT[(size_t)DD * DD];     // W_out^T lo
// flash operands: Q,K [bh][S][64]; V transposed [bh][64][S]
__device__ __nv_bfloat16 g_qhi[(size_t)BB * HH * SS * HD];
__device__ __nv_bfloat16 g_qlo[(size_t)BB * HH * SS * HD];
__device__ __nv_bfloat16 g_khi[(size_t)BB * HH * SS * HD];
__device__ __nv_bfloat16 g_klo[(size_t)BB * HH * SS * HD];
__device__ __nv_bfloat16 g_vth[(size_t)BB * HH * HD * SS];
__device__ __nv_bfloat16 g_vtl[(size_t)BB * HH * HD * SS];

// ---------------------------------------------------------------------------
// PTX helpers (portable: mma.sync / ldmatrix / cp.async — no arch-'a' features)
// ---------------------------------------------------------------------------
__device__ __forceinline__ uint32_t smem_to_u32(const void* smem_ptr) {
    uint32_t addr;
    asm("{ .reg .u64 tmp; cvta.to.shared.u64 tmp, %1; cvt.u32.u64 %0, tmp; }"
        : "=r"(addr) : "l"(smem_ptr));
    return addr;
}
__device__ __forceinline__ void ldsm4(uint32_t* r, uint32_t addr) {
    asm volatile("ldmatrix.sync.aligned.m8n8.x4.shared.b16 {%0,%1,%2,%3}, [%4];"
                 : "=r"(r[0]), "=r"(r[1]), "=r"(r[2]), "=r"(r[3]) : "r"(addr));
}
__device__ __forceinline__ void mma16816(float* c, const uint32_t* a, const uint32_t* b) {
    asm volatile(
        "mma.sync.aligned.m16n8k16.row.col.f32.bf16.bf16.f32 "
        "{%0,%1,%2,%3}, {%4,%5,%6,%7}, {%8,%9}, {%0,%1,%2,%3};"
        : "+f"(c[0]), "+f"(c[1]), "+f"(c[2]), "+f"(c[3])
        : "r"(a[0]), "r"(a[1]), "r"(a[2]), "r"(a[3]), "r"(b[0]), "r"(b[1]));
}
__device__ __forceinline__ uint32_t packbf(float lo, float hi) {
    uint32_t d;
    asm("cvt.rn.bf16x2.f32 %0, %1, %2;" : "=r"(d) : "f"(hi), "f"(lo));
    return d;
}
#define CP_ASYNC16(sm_u32, gptr) \
    asm volatile("cp.async.cg.shared.global [%0], [%1], 16;" :: "r"(sm_u32), "l"(gptr))
#define CP_COMMIT() asm volatile("cp.async.commit_group;" ::: "memory")
#define CP_WAIT1()  asm volatile("cp.async.wait_group 1;" ::: "memory")
#define CP_WAIT0()  asm volatile("cp.async.wait_group 0;" ::: "memory")

// ---------------------------------------------------------------------------
// Split/convert kernels
// ---------------------------------------------------------------------------
__global__ void split_k(const float* __restrict__ in,
                        __nv_bfloat16* __restrict__ hi,
                        __nv_bfloat16* __restrict__ lo, int n)
{
    int i = blockIdx.x * blockDim.x + threadIdx.x;
    if (i >= n) return;
    float v = in[i];
    __nv_bfloat16 h = __float2bfloat16_rn(v);
    hi[i] = h;
    lo[i] = __float2bfloat16_rn(v - __bfloat162float(h));
}

// Transpose + split: in [K][N] fp32 -> hiT/loT [N][K] bf16
__global__ __launch_bounds__(256) void tsplit_k(const float* __restrict__ in,
                                                __nv_bfloat16* __restrict__ hiT,
                                                __nv_bfloat16* __restrict__ loT,
                                                int K, int N)
{
    __shared__ float tile[32][33];
    const int tx = threadIdx.x & 31;
    const int ty = threadIdx.x >> 5;       // 0..7
    const int n0 = blockIdx.x * 32;
    const int k0 = blockIdx.y * 32;
#pragma unroll
    for (int i = 0; i < 4; i++) {
        int kk = ty + 8 * i;
        tile[kk][tx] = in[(size_t)(k0 + kk) * N + n0 + tx];
    }
    __syncthreads();
#pragma unroll
    for (int i = 0; i < 4; i++) {
        int nn = ty + 8 * i;
        float v = tile[tx][nn];
        __nv_bfloat16 h = __float2bfloat16_rn(v);
        size_t o = (size_t)(n0 + nn) * K + k0 + tx;
        hiT[o] = h;
        loT[o] = __float2bfloat16_rn(v - __bfloat162float(h));
    }
}

// ---------------------------------------------------------------------------
// HMMA bf16-split GEMM (unchanged from round 4 — passing)
// ---------------------------------------------------------------------------
#define KC 32
#define NKC (GK / KC)            // 32
#define ROWB 80                  // 32 bf16 = 64B data + 16B pad
#define TILE_SB (128 * ROWB)     // 10240
#define STAGE_SB (4 * TILE_SB)   // 40960
#define GEMM_SMEM_SZ (2 * STAGE_SB)  // 81920

__global__ __launch_bounds__(256) void gemm_hmma_k(
    const __nv_bfloat16* __restrict__ ahi, const __nv_bfloat16* __restrict__ alo,
    const __nv_bfloat16* __restrict__ bhiT, const __nv_bfloat16* __restrict__ bloT,
    float* __restrict__ C, int N)
{
    extern __shared__ char sm[];
    const uint32_t sb = smem_to_u32(sm);
    const int t = threadIdx.x;
    const int lane = t & 31;
    const int wid = t >> 5;
    const int wm = wid & 1;
    const int wn = wid >> 1;
    const size_t arow0 = (size_t)blockIdx.y * 128;
    const size_t brow0 = (size_t)blockIdx.x * 128;

    const __nv_bfloat16* gsrc[4] = {
        ahi + arow0 * GK, alo + arow0 * GK,
        bhiT + brow0 * GK, bloT + brow0 * GK };

    auto issue_stage = [&](int c) {
        const uint32_t st = sb + (c & 1) * STAGE_SB;
        const size_t k0 = (size_t)c * KC;
#pragma unroll
        for (int comp = 0; comp < 4; comp++) {
#pragma unroll
            for (int i = 0; i < 2; i++) {
                int u = t + i * 256;
                int r = u >> 2, ch = u & 3;
                const void* g = gsrc[comp] + (size_t)r * GK + k0 + ch * 8;
                CP_ASYNC16(st + comp * TILE_SB + r * ROWB + ch * 16, g);
            }
        }
        CP_COMMIT();
    };

    float acc[4][4][4];
#pragma unroll
    for (int mt = 0; mt < 4; mt++)
#pragma unroll
        for (int nt = 0; nt < 4; nt++)
#pragma unroll
            for (int i = 0; i < 4; i++) acc[mt][nt][i] = 0.f;

    issue_stage(0);
    issue_stage(1);

    const int idx = lane & 7;
    const int sel = lane >> 3;

    for (int c = 0; c < NKC; c++) {
        if (c + 1 < NKC) { CP_WAIT1(); } else { CP_WAIT0(); }
        __syncthreads();
        const uint32_t st = sb + (c & 1) * STAGE_SB;

#pragma unroll
        for (int j = 0; j < 2; j++) {
            uint32_t ahif[4][4], alof[4][4], bhif[4][2], blof[4][2];
            const uint32_t acol = (uint32_t)((2 * j + (sel >> 1)) << 4);
#pragma unroll
            for (int mt = 0; mt < 4; mt++) {
                uint32_t ra = (uint32_t)(wm * 64 + mt * 16 + ((sel & 1) << 3) + idx);
                uint32_t ad = st + ra * ROWB + acol;
                ldsm4(ahif[mt], ad);
                ldsm4(alof[mt], ad + TILE_SB);
            }
            {
                const uint32_t bcol = (uint32_t)((2 * j + (sel & 1)) << 4);
                uint32_t rb = (uint32_t)(wn * 32 + ((sel >> 1) << 3) + idx);
                uint32_t bd = st + 2 * TILE_SB + rb * ROWB + bcol;
                uint32_t tmp[4];
                ldsm4(tmp, bd);
                bhif[0][0] = tmp[0]; bhif[0][1] = tmp[1];
                bhif[1][0] = tmp[2]; bhif[1][1] = tmp[3];
                ldsm4(tmp, bd + 16 * ROWB);
                bhif[2][0] = tmp[0]; bhif[2][1] = tmp[1];
                bhif[3][0] = tmp[2]; bhif[3][1] = tmp[3];
                ldsm4(tmp, bd + TILE_SB);
                blof[0][0] = tmp[0]; blof[0][1] = tmp[1];
                blof[1][0] = tmp[2]; blof[1][1] = tmp[3];
                ldsm4(tmp, bd + TILE_SB + 16 * ROWB);
                blof[2][0] = tmp[0]; blof[2][1] = tmp[1];
                blof[3][0] = tmp[2]; blof[3][1] = tmp[3];
            }
#pragma unroll
            for (int mt = 0; mt < 4; mt++)
#pragma unroll
                for (int nt = 0; nt < 4; nt++) {
                    mma16816(acc[mt][nt], ahif[mt], bhif[nt]);
                    mma16816(acc[mt][nt], ahif[mt], blof[nt]);
                    mma16816(acc[mt][nt], alof[mt], bhif[nt]);
                }
        }
        __syncthreads();
        if (c + 2 < NKC) issue_stage(c + 2);
    }

    const int g = lane >> 2, tg = lane & 3;
#pragma unroll
    for (int mt = 0; mt < 4; mt++) {
        size_t row0 = arow0 + wm * 64 + mt * 16 + g;
#pragma unroll
        for (int nt = 0; nt < 4; nt++) {
            size_t col = brow0 + wn * 32 + nt * 8 + tg * 2;
            *(float2*)(C + row0 * N + col) = make_float2(acc[mt][nt][0], acc[mt][nt][1]);
            *(float2*)(C + (row0 + 8) * N + col) = make_float2(acc[mt][nt][2], acc[mt][nt][3]);
        }
    }
}

// ---------------------------------------------------------------------------
// RoPE + split: reads g_qkv, rotates q (scaled) and k, writes bf16 hi/lo in
// flash layout [bh][S][64].
// ---------------------------------------------------------------------------
__global__ void ropesplit_k(const int* __restrict__ pos)
{
    int idx = blockIdx.x * blockDim.x + threadIdx.x;
    const int total = ROWS * HH * 2 * 32;
    if (idx >= total) return;
    int i = idx & 31;
    int rest = idx >> 5;
    int comp = rest & 1; rest >>= 1;   // 0 = q, 1 = k
    int h = rest & 15;
    int row = rest >> 4;
    int b = row >> 11;                 // / SS
    int s = row & (SS - 1);
    int bh = b * HH + h;

    float p = (float)pos[row];
    float inv = powf(10000.0f, -(float)i * (1.0f / 32.0f));
    float sn, cs;
    sincosf(p * inv, &sn, &cs);

    const float* base = g_qkv + (size_t)row * (3 * DD) + h * TRIPLE + comp * HD;
    float x1 = base[i];
    float x2 = base[i + 32];
    float o1 = x1 * cs - x2 * sn;
    float o2 = x1 * sn + x2 * cs;
    if (comp == 0) { o1 *= 0.125f; o2 *= 0.125f; }

    __nv_bfloat16* dh = (comp ? g_khi : g_qhi) + ((size_t)bh * SS + s) * HD;
    __nv_bfloat16* dl = (comp ? g_klo : g_qlo) + ((size_t)bh * SS + s) * HD;
    __nv_bfloat16 h1 = __float2bfloat16_rn(o1);
    dh[i] = h1;
    dl[i] = __float2bfloat16_rn(o1 - __bfloat162float(h1));
    __nv_bfloat16 h2 = __float2bfloat16_rn(o2);
    dh[i + 32] = h2;
    dl[i + 32] = __float2bfloat16_rn(o2 - __bfloat162float(h2));
}

// ---------------------------------------------------------------------------
// V transpose + split: g_qkv v-part -> g_vth/g_vtl [bh][64][S]
// grid (BH, S/64), 256 threads
// ---------------------------------------------------------------------------
__global__ __launch_bounds__(256) void vsplit_k()
{
    __shared__ float tile[64][65];
    const int bh = blockIdx.x;
    const int b = bh >> 4, h = bh & 15;
    const int s0 = blockIdx.y * 64;
    const int t = threadIdx.x;
#pragma unroll
    for (int i = 0; i < 16; i++) {
        int u = t + i * 256;
        int sl = u >> 6, d = u & 63;
        tile[sl][d] = g_qkv[(size_t)(b * SS + s0 + sl) * (3 * DD) + h * TRIPLE + 2 * HD + d];
    }
    __syncthreads();
#pragma unroll
    for (int i = 0; i < 16; i++) {
        int u = t + i * 256;
        int dl = u >> 6, sl = u & 63;
        float v = tile[sl][dl];
        __nv_bfloat16 hh = __float2bfloat16_rn(v);
        size_t o = ((size_t)bh * HD + dl) * SS + s0 + sl;
        g_vth[o] = hh;
        g_vtl[o] = __float2bfloat16_rn(v - __bfloat162float(hh));
    }
}

// ---------------------------------------------------------------------------
// HMMA causal flash attention.
// grid (S/128, BH), 256 threads (8 warps, warp = m16 q-tile).
// Q [128][64] hi/lo resident in smem; K/V 64-key tiles double-buffered.
// 3-term bf16 split on QK^T and PV. Epilogue writes bf16 hi/lo (chi/clo).
// ---------------------------------------------------------------------------
#define FQ 128
#define FKT 64
#define FSQH 0
#define FSQL 16384
#define FSKV 32768
#define FBUF 32768
#define FLASH_SMEM 98304

__device__ __forceinline__ uint32_t fsw(int r, int c) {
    return (uint32_t)((r << 7) + (((c ^ (r & 7))) << 4));
}

__global__ __launch_bounds__(256) void flashmma_k()
{
    extern __shared__ char sm[];
    const uint32_t sb = smem_to_u32(sm);
    const int t = threadIdx.x, lane = t & 31, w = t >> 5;
    const int idx = lane & 7, sel = lane >> 3;
    const int bh = blockIdx.y, b = bh >> 4, h = bh & 15;
    const int qt = (int)gridDim.x - 1 - (int)blockIdx.x;   // heavy tiles first
    const int q0 = qt * FQ;
    const int qw = q0 + w * 16;
    const int ntiles = q0 / FKT + 2;

    // Q tile cp.async (hi/lo)
    {
        const __nv_bfloat16* s0 = g_qhi + ((size_t)bh * SS + q0) * HD;
        const __nv_bfloat16* s1 = g_qlo + ((size_t)bh * SS + q0) * HD;
#pragma unroll
        for (int i = 0; i < 4; i++) {
            int u = t + i * 256; int r = u >> 3, c = u & 7;
            CP_ASYNC16(sb + FSQH + fsw(r, c), s0 + (size_t)r * HD + c * 8);
        }
#pragma unroll
        for (int i = 0; i < 4; i++) {
            int u = t + i * 256; int r = u >> 3, c = u & 7;
            CP_ASYNC16(sb + FSQL + fsw(r, c), s1 + (size_t)r * HD + c * 8);
        }
        CP_COMMIT();
    }

    auto ld_kv = [&](int ct) {
        const int k0 = ct * FKT;
        const uint32_t bd = sb + FSKV + (ct & 1) * FBUF;
        const __nv_bfloat16* sk0 = g_khi + ((size_t)bh * SS + k0) * HD;
        const __nv_bfloat16* sk1 = g_klo + ((size_t)bh * SS + k0) * HD;
#pragma unroll
        for (int i = 0; i < 2; i++) {
            int u = t + i * 256; int r = u >> 3, c = u & 7;
            CP_ASYNC16(bd + fsw(r, c), sk0 + (size_t)r * HD + c * 8);
            CP_ASYNC16(bd + 8192 + fsw(r, c), sk1 + (size_t)r * HD + c * 8);
        }
        const __nv_bfloat16* sv0 = g_vth + (size_t)bh * HD * SS + k0;
        const __nv_bfloat16* sv1 = g_vtl + (size_t)bh * HD * SS + k0;
#pragma unroll
        for (int i = 0; i < 2; i++) {
            int u = t + i * 256; int r = u >> 3, c = u & 7;
            CP_ASYNC16(bd + 16384 + fsw(r, c), sv0 + (size_t)r * SS + c * 8);
            CP_ASYNC16(bd + 24576 + fsw(r, c), sv1 + (size_t)r * SS + c * 8);
        }
        CP_COMMIT();
    };

    ld_kv(0);
    CP_WAIT0();
    __syncthreads();

    // Q fragments (resident): 4 k16 chunks, hi+lo
    uint32_t qhf[4][4], qlf[4][4];
#pragma unroll
    for (int j = 0; j < 4; j++) {
        int row = w * 16 + ((sel & 1) << 3) + idx;
        int ch = 2 * j + (sel >> 1);
        ldsm4(qhf[j], sb + FSQH + fsw(row, ch));
        ldsm4(qlf[j], sb + FSQL + fsw(row, ch));
    }

    float o[8][4];
#pragma unroll
    for (int nt = 0; nt < 8; nt++)
#pragma unroll
        for (int i = 0; i < 4; i++) o[nt][i] = 0.f;
    float m0 = -INFINITY, m1 = -INFINITY, l0 = 0.f, l1 = 0.f;
    const int r = lane >> 2, cb = (lane & 3) * 2;

    for (int c = 0; c < ntiles; c++) {
        if (c + 1 < ntiles) ld_kv(c + 1);
        const int k0 = c * FKT;
        const uint32_t kb = sb + FSKV + (c & 1) * FBUF;

        if (k0 <= qw + 15) {
            float s[8][4];
#pragma unroll
            for (int nt = 0; nt < 8; nt++)
#pragma unroll
                for (int i = 0; i < 4; i++) s[nt][i] = 0.f;

            // S = Q K^T (3-term)
#pragma unroll
            for (int j = 0; j < 4; j++) {
                const int krow = ((sel >> 1) << 3) + idx;
                const int kch = 2 * j + (sel & 1);
#pragma unroll
                for (int np = 0; np < 4; np++) {
                    uint32_t th[4], tl[4];
                    ldsm4(th, kb + fsw(np * 16 + krow, kch));
                    ldsm4(tl, kb + 8192 + fsw(np * 16 + krow, kch));
                    uint32_t b0h[2] = { th[0], th[1] }, b1h[2] = { th[2], th[3] };
                    uint32_t b0l[2] = { tl[0], tl[1] }, b1l[2] = { tl[2], tl[3] };
                    mma16816(s[2 * np],     qhf[j], b0h);
                    mma16816(s[2 * np],     qhf[j], b0l);
                    mma16816(s[2 * np],     qlf[j], b0h);
                    mma16816(s[2 * np + 1], qhf[j], b1h);
                    mma16816(s[2 * np + 1], qhf[j], b1l);
                    mma16816(s[2 * np + 1], qlf[j], b1h);
                }
            }
            // causal mask
            if (k0 + FKT - 1 > qw) {
                const int row0 = qw + r, row1 = row0 + 8;
#pragma unroll
                for (int nt = 0; nt < 8; nt++) {
                    int c0 = k0 + nt * 8 + cb;
                    if (c0 > row0)     s[nt][0] = -INFINITY;
                    if (c0 + 1 > row0) s[nt][1] = -INFINITY;
                    if (c0 > row1)     s[nt][2] = -INFINITY;
                    if (c0 + 1 > row1) s[nt][3] = -INFINITY;
                }
            }
            // online softmax
            float mx0 = s[0][0], mx1 = s[0][2];
#pragma unroll
            for (int nt = 0; nt < 8; nt++) {
                mx0 = fmaxf(mx0, fmaxf(s[nt][0], s[nt][1]));
                mx1 = fmaxf(mx1, fmaxf(s[nt][2], s[nt][3]));
            }
            mx0 = fmaxf(mx0, __shfl_xor_sync(0xffffffffu, mx0, 1));
            mx0 = fmaxf(mx0, __shfl_xor_sync(0xffffffffu, mx0, 2));
            mx1 = fmaxf(mx1, __shfl_xor_sync(0xffffffffu, mx1, 1));
            mx1 = fmaxf(mx1, __shfl_xor_sync(0xffffffffu, mx1, 2));
            float mn0 = fmaxf(m0, mx0), mn1 = fmaxf(m1, mx1);
            float sc0 = __expf(m0 - mn0), sc1 = __expf(m1 - mn1);
            float rs0 = 0.f, rs1 = 0.f;
#pragma unroll
            for (int nt = 0; nt < 8; nt++) {
                s[nt][0] = __expf(s[nt][0] - mn0); rs0 += s[nt][0];
                s[nt][1] = __expf(s[nt][1] - mn0); rs0 += s[nt][1];
                s[nt][2] = __expf(s[nt][2] - mn1); rs1 += s[nt][2];
                s[nt][3] = __expf(s[nt][3] - mn1); rs1 += s[nt][3];
            }
            rs0 += __shfl_xor_sync(0xffffffffu, rs0, 1);
            rs0 += __shfl_xor_sync(0xffffffffu, rs0, 2);
            rs1 += __shfl_xor_sync(0xffffffffu, rs1, 1);
            rs1 += __shfl_xor_sync(0xffffffffu, rs1, 2);
            m0 = mn0; m1 = mn1;
            l0 = l0 * sc0 + rs0; l1 = l1 * sc1 + rs1;
#pragma unroll
            for (int nt = 0; nt < 8; nt++) {
                o[nt][0] *= sc0; o[nt][1] *= sc0;
                o[nt][2] *= sc1; o[nt][3] *= sc1;
            }
            // O += P V (3-term); P A-fragments from S fragments
#pragma unroll
            for (int j = 0; j < 4; j++) {
                uint32_t pah[4], pal[4];
                {
                    uint32_t p0; float r0, r1;
                    p0 = packbf(s[2 * j][0], s[2 * j][1]);
                    r0 = s[2 * j][0] - __uint_as_float(p0 << 16);
                    r1 = s[2 * j][1] - __uint_as_float(p0 & 0xFFFF0000u);
                    pah[0] = p0; pal[0] = packbf(r0, r1);
                    p0 = packbf(s[2 * j][2], s[2 * j][3]);
                    r0 = s[2 * j][2] - __uint_as_float(p0 << 16);
                    r1 = s[2 * j][3] - __uint_as_float(p0 & 0xFFFF0000u);
                    pah[1] = p0; pal[1] = packbf(r0, r1);
                    p0 = packbf(s[2 * j + 1][0], s[2 * j + 1][1]);
                    r0 = s[2 * j + 1][0] - __uint_as_float(p0 << 16);
                    r1 = s[2 * j + 1][1] - __uint_as_float(p0 & 0xFFFF0000u);
                    pah[2] = p0; pal[2] = packbf(r0, r1);
                    p0 = packbf(s[2 * j + 1][2], s[2 * j + 1][3]);
                    r0 = s[2 * j + 1][2] - __uint_as_float(p0 << 16);
                    r1 = s[2 * j + 1][3] - __uint_as_float(p0 & 0xFFFF0000u);
                    pah[3] = p0; pal[3] = packbf(r0, r1);
                }
                const int vrow = ((sel >> 1) << 3) + idx;
                const int vch = 2 * j + (sel & 1);
#pragma unroll
                for (int np = 0; np < 4; np++) {
                    uint32_t th[4], tl[4];
                    ldsm4(th, kb + 16384 + fsw(np * 16 + vrow, vch));
                    ldsm4(tl, kb + 24576 + fsw(np * 16 + vrow, vch));
                    uint32_t b0h[2] = { th[0], th[1] }, b1h[2] = { th[2], th[3] };
                    uint32_t b0l[2] = { tl[0], tl[1] }, b1l[2] = { tl[2], tl[3] };
                    mma16816(o[2 * np],     pah, b0h);
                    mma16816(o[2 * np],     pah, b0l);
                    mma16816(o[2 * np],     pal, b0h);
                    mma16816(o[2 * np + 1], pah, b1h);
                    mma16816(o[2 * np + 1], pah, b1l);
                    mma16816(o[2 * np + 1], pal, b1h);
                }
            }
        }
        __syncthreads();
        if (c + 1 < ntiles) { CP_WAIT0(); __syncthreads(); }
    }

    // epilogue: normalize, split to bf16 hi/lo, write chi/clo [row][h*64+d]
    float i0 = 1.f / l0, i1 = 1.f / l1;
    const size_t row0 = (size_t)b * SS + qw + r;
    const size_t row1 = row0 + 8;
#pragma unroll
    for (int nt = 0; nt < 8; nt++) {
        int col = h * HD + nt * 8 + cb;
        float a0 = o[nt][0] * i0, a1 = o[nt][1] * i0;
        uint32_t p = packbf(a0, a1);
        float r0 = a0 - __uint_as_float(p << 16);
        float r1 = a1 - __uint_as_float(p & 0xFFFF0000u);
        *(uint32_t*)(g_chi + row0 * DD + col) = p;
        *(uint32_t*)(g_clo + row0 * DD + col) = packbf(r0, r1);
        a0 = o[nt][2] * i1; a1 = o[nt][3] * i1;
        p = packbf(a0, a1);
        r0 = a0 - __uint_as_float(p << 16);
        r1 = a1 - __uint_as_float(p & 0xFFFF0000u);
        *(uint32_t*)(g_chi + row1 * DD + col) = p;
        *(uint32_t*)(g_clo + row1 * DD + col) = packbf(r0, r1);
    }
}

// ---------------------------------------------------------------------------
// Launch
// Inputs: 0=inputs f32[B,S,D], 1=segment_positions i32[B,S], 2=mask (unused),
// 3=W_in f32[D,3D], 4=W_out f32[D,D]. Output: f32[B,S,D].
// ---------------------------------------------------------------------------
extern "C" void kernel_launch(void* const* d_in, const int* in_sizes, int n_in,
                              void* d_out, int out_size)
{
    const float* x    = (const float*)d_in[0];
    const int*   pos  = (const int*)d_in[1];
    const float* Win  = (const float*)d_in[3];
    const float* Wout = (const float*)d_in[4];
    float* out = (float*)d_out;

    float* qkv;
    __nv_bfloat16 *ahi, *alo, *chi, *clo, *whiT, *wloT, *ohiT, *oloT;
    cudaGetSymbolAddress((void**)&qkv, g_qkv);
    cudaGetSymbolAddress((void**)&ahi, g_ahi);
    cudaGetSymbolAddress((void**)&alo, g_alo);
    cudaGetSymbolAddress((void**)&chi, g_chi);
    cudaGetSymbolAddress((void**)&clo, g_clo);
    cudaGetSymbolAddress((void**)&whiT, g_whiT);
    cudaGetSymbolAddress((void**)&wloT, g_wloT);
    cudaGetSymbolAddress((void**)&ohiT, g_ohiT);
    cudaGetSymbolAddress((void**)&oloT, g_oloT);

    cudaFuncSetAttribute(gemm_hmma_k,
                         cudaFuncAttributeMaxDynamicSharedMemorySize, GEMM_SMEM_SZ);
    cudaFuncSetAttribute(flashmma_k,
                         cudaFuncAttributeMaxDynamicSharedMemorySize, FLASH_SMEM);

    // 0) split inputs, transpose+split weights
    {
        int n = ROWS * DD;
        split_k<<<(n + 255) / 256, 256>>>(x, ahi, alo, n);
    }
    tsplit_k<<<dim3(3 * DD / 32, DD / 32), 256>>>(Win, whiT, wloT, DD, 3 * DD);
    tsplit_k<<<dim3(DD / 32, DD / 32), 256>>>(Wout, ohiT, oloT, DD, DD);

    // 1) QKV projection via HMMA
    gemm_hmma_k<<<dim3(3 * DD / 128, ROWS / 128), 256, GEMM_SMEM_SZ>>>(
        ahi, alo, whiT, wloT, qkv, 3 * DD);

    // 2) RoPE + bf16 hi/lo split into flash layouts; V transpose+split
    {
        int nrope = ROWS * HH * 2 * 32;
        ropesplit_k<<<(nrope + 255) / 256, 256>>>(pos);
    }
    vsplit_k<<<dim3(BB * HH, SS / 64), 256>>>();

    // 3) HMMA causal flash attention (writes chi/clo directly)
    flashmma_k<<<dim3(SS / FQ, BB * HH), 256, FLASH_SMEM>>>();

    // 4) Output projection via HMMA
    gemm_hmma_k<<<dim3(DD / 128, ROWS / 128), 256, GEMM_SMEM_SZ>>>(
        chi, clo, ohiT, oloT, out, DD);
}

// round 7
// speedup vs baseline: 4.4141x; 1.2460x over previous
#include <cuda_runtime.h>
#include <cuda_bf16.h>
#include <cuda_fp16.h>
#include <math.h>
#include <stdint.h>

#define BB 2
#define SS 2048
#define DD 1024
#define HH 16
#define HD 64
#define ROWS (BB*SS)      // 4096
#define TRIPLE (3*HD)     // 192 floats per (row, head)
#define GK 1024           // GEMM K dim (fixed)

// ---------------------------------------------------------------------------
// Scratch (static device globals; no allocation at runtime)
// ---------------------------------------------------------------------------
__device__ float g_qkv[(size_t)ROWS * 3 * DD];        // [ROWS][H][192] fp32
__device__ __half g_ahi[(size_t)ROWS * DD];           // inputs split hi [row][K]
__device__ __half g_alo[(size_t)ROWS * DD];           // inputs split lo
__device__ __half g_chi[(size_t)ROWS * DD];           // attn out split hi [row][D]
__device__ __half g_clo[(size_t)ROWS * DD];           // attn out split lo
__device__ __half g_wT[(size_t)3 * DD * DD];          // W_in^T fp16 [3072][1024]
__device__ __half g_oT[(size_t)DD * DD];              // W_out^T fp16 [1024][1024]
// flash operands (bf16 3-term path): Q,K [bh][S][64]; V^T [bh][64][S]
__device__ __nv_bfloat16 g_qhi[(size_t)BB * HH * SS * HD];
__device__ __nv_bfloat16 g_qlo[(size_t)BB * HH * SS * HD];
__device__ __nv_bfloat16 g_khi[(size_t)BB * HH * SS * HD];
__device__ __nv_bfloat16 g_klo[(size_t)BB * HH * SS * HD];
__device__ __nv_bfloat16 g_vth[(size_t)BB * HH * HD * SS];
__device__ __nv_bfloat16 g_vtl[(size_t)BB * HH * HD * SS];

// ---------------------------------------------------------------------------
// PTX helpers (portable: mma.sync / ldmatrix / cp.async — no arch-'a' features)
// ---------------------------------------------------------------------------
__device__ __forceinline__ uint32_t smem_to_u32(const void* smem_ptr) {
    uint32_t addr;
    asm("{ .reg .u64 tmp; cvta.to.shared.u64 tmp, %1; cvt.u32.u64 %0, tmp; }"
        : "=r"(addr) : "l"(smem_ptr));
    return addr;
}
__device__ __forceinline__ void ldsm4(uint32_t* r, uint32_t addr) {
    asm volatile("ldmatrix.sync.aligned.m8n8.x4.shared.b16 {%0,%1,%2,%3}, [%4];"
                 : "=r"(r[0]), "=r"(r[1]), "=r"(r[2]), "=r"(r[3]) : "r"(addr));
}
__device__ __forceinline__ void mma16816(float* c, const uint32_t* a, const uint32_t* b) {
    asm volatile(
        "mma.sync.aligned.m16n8k16.row.col.f32.bf16.bf16.f32 "
        "{%0,%1,%2,%3}, {%4,%5,%6,%7}, {%8,%9}, {%0,%1,%2,%3};"
        : "+f"(c[0]), "+f"(c[1]), "+f"(c[2]), "+f"(c[3])
        : "r"(a[0]), "r"(a[1]), "r"(a[2]), "r"(a[3]), "r"(b[0]), "r"(b[1]));
}
__device__ __forceinline__ void mma16816h(float* c, const uint32_t* a, const uint32_t* b) {
    asm volatile(
        "mma.sync.aligned.m16n8k16.row.col.f32.f16.f16.f32 "
        "{%0,%1,%2,%3}, {%4,%5,%6,%7}, {%8,%9}, {%0,%1,%2,%3};"
        : "+f"(c[0]), "+f"(c[1]), "+f"(c[2]), "+f"(c[3])
        : "r"(a[0]), "r"(a[1]), "r"(a[2]), "r"(a[3]), "r"(b[0]), "r"(b[1]));
}
__device__ __forceinline__ uint32_t packbf(float lo, float hi) {
    uint32_t d;
    asm("cvt.rn.bf16x2.f32 %0, %1, %2;" : "=r"(d) : "f"(hi), "f"(lo));
    return d;
}
__device__ __forceinline__ uint32_t packh(float lo, float hi) {
    __half2 h = __floats2half2_rn(lo, hi);
    return *(uint32_t*)&h;
}
#define CP_ASYNC16(sm_u32, gptr) \
    asm volatile("cp.async.cg.shared.global [%0], [%1], 16;" :: "r"(sm_u32), "l"(gptr))
#define CP_COMMIT() asm volatile("cp.async.commit_group;" ::: "memory")
#define CP_WAIT1()  asm volatile("cp.async.wait_group 1;" ::: "memory")
#define CP_WAIT0()  asm volatile("cp.async.wait_group 0;" ::: "memory")

// ---------------------------------------------------------------------------
// Split/convert kernels
// ---------------------------------------------------------------------------
__global__ void split_k(const float* __restrict__ in,
                        __half* __restrict__ hi,
                        __half* __restrict__ lo, int n)
{
    int i = blockIdx.x * blockDim.x + threadIdx.x;
    if (i >= n) return;
    float v = in[i];
    __half h = __float2half_rn(v);
    hi[i] = h;
    lo[i] = __float2half_rn(v - __half2float(h));
}

// Transpose + round: in [K][N] fp32 -> outT [N][K] fp16
__global__ __launch_bounds__(256) void tsplit_k(const float* __restrict__ in,
                                                __half* __restrict__ outT,
                                                int K, int N)
{
    __shared__ float tile[32][33];
    const int tx = threadIdx.x & 31;
    const int ty = threadIdx.x >> 5;       // 0..7
    const int n0 = blockIdx.x * 32;
    const int k0 = blockIdx.y * 32;
#pragma unroll
    for (int i = 0; i < 4; i++) {
        int kk = ty + 8 * i;
        tile[kk][tx] = in[(size_t)(k0 + kk) * N + n0 + tx];
    }
    __syncthreads();
#pragma unroll
    for (int i = 0; i < 4; i++) {
        int nn = ty + 8 * i;
        outT[(size_t)(n0 + nn) * K + k0 + tx] = __float2half_rn(tile[tx][nn]);
    }
}

// ---------------------------------------------------------------------------
// HMMA fp16 2-term GEMM: C[M,N] = (Ahi+Alo)[M,K] * B^T  (B given fp16 [N][K])
// 128x128 block, 8 warps (warp tile 64x32), KC=32, 3-stage cp.async pipeline,
// one __syncthreads per k-iteration.
// ---------------------------------------------------------------------------
#define KC 32
#define NKC (GK / KC)            // 32
#define ROWB 80                  // 32 fp16 = 64B data + 16B pad
#define TILE_SB (128 * ROWB)     // 10240
#define STAGE_SB (3 * TILE_SB)   // Ahi, Alo, B = 30720
#define NSTG 3
#define GEMM_SMEM_SZ (NSTG * STAGE_SB)  // 92160

__global__ __launch_bounds__(256) void gemm_hmma_k(
    const __half* __restrict__ ahi, const __half* __restrict__ alo,
    const __half* __restrict__ bT,
    float* __restrict__ C, int N)
{
    extern __shared__ char sm[];
    const uint32_t sb = smem_to_u32(sm);
    const int t = threadIdx.x;
    const int lane = t & 31;
    const int wid = t >> 5;
    const int wm = wid & 1;
    const int wn = wid >> 1;
    const size_t arow0 = (size_t)blockIdx.y * 128;
    const size_t brow0 = (size_t)blockIdx.x * 128;

    const __half* gsrc[3] = {
        ahi + arow0 * GK, alo + arow0 * GK, bT + brow0 * GK };

    auto issue_stage = [&](int c) {
        const uint32_t st = sb + (uint32_t)(c % NSTG) * STAGE_SB;
        const size_t k0 = (size_t)c * KC;
#pragma unroll
        for (int comp = 0; comp < 3; comp++) {
#pragma unroll
            for (int i = 0; i < 2; i++) {
                int u = t + i * 256;
                int r = u >> 2, ch = u & 3;
                const void* g = gsrc[comp] + (size_t)r * GK + k0 + ch * 8;
                CP_ASYNC16(st + comp * TILE_SB + r * ROWB + ch * 16, g);
            }
        }
    };

    float acc[4][4][4];
#pragma unroll
    for (int mt = 0; mt < 4; mt++)
#pragma unroll
        for (int nt = 0; nt < 4; nt++)
#pragma unroll
            for (int i = 0; i < 4; i++) acc[mt][nt][i] = 0.f;

    issue_stage(0); CP_COMMIT();
    issue_stage(1); CP_COMMIT();
    CP_WAIT1();
    __syncthreads();

    const int idx = lane & 7;
    const int sel = lane >> 3;

    for (int c = 0; c < NKC; c++) {
        if (c + 2 < NKC) issue_stage(c + 2);
        CP_COMMIT();                         // one group per iteration, always
        const uint32_t st = sb + (uint32_t)(c % NSTG) * STAGE_SB;

#pragma unroll
        for (int j = 0; j < 2; j++) {
            uint32_t ahif[4][4], alof[4][4], bf[4][2];
            const uint32_t acol = (uint32_t)((2 * j + (sel >> 1)) << 4);
#pragma unroll
            for (int mt = 0; mt < 4; mt++) {
                uint32_t ra = (uint32_t)(wm * 64 + mt * 16 + ((sel & 1) << 3) + idx);
                uint32_t ad = st + ra * ROWB + acol;
                ldsm4(ahif[mt], ad);
                ldsm4(alof[mt], ad + TILE_SB);
            }
            {
                const uint32_t bcol = (uint32_t)((2 * j + (sel & 1)) << 4);
                uint32_t rb = (uint32_t)(wn * 32 + ((sel >> 1) << 3) + idx);
                uint32_t bd = st + 2 * TILE_SB + rb * ROWB + bcol;
                uint32_t tmp[4];
                ldsm4(tmp, bd);
                bf[0][0] = tmp[0]; bf[0][1] = tmp[1];
                bf[1][0] = tmp[2]; bf[1][1] = tmp[3];
                ldsm4(tmp, bd + 16 * ROWB);
                bf[2][0] = tmp[0]; bf[2][1] = tmp[1];
                bf[3][0] = tmp[2]; bf[3][1] = tmp[3];
            }
#pragma unroll
            for (int mt = 0; mt < 4; mt++)
#pragma unroll
                for (int nt = 0; nt < 4; nt++) {
                    mma16816h(acc[mt][nt], ahif[mt], bf[nt]);
                    mma16816h(acc[mt][nt], alof[mt], bf[nt]);
                }
        }
        CP_WAIT1();                          // next stage resident
        __syncthreads();
    }

    const int g = lane >> 2, tg = lane & 3;
#pragma unroll
    for (int mt = 0; mt < 4; mt++) {
        size_t row0 = arow0 + wm * 64 + mt * 16 + g;
#pragma unroll
        for (int nt = 0; nt < 4; nt++) {
            size_t col = brow0 + wn * 32 + nt * 8 + tg * 2;
            *(float2*)(C + row0 * N + col) = make_float2(acc[mt][nt][0], acc[mt][nt][1]);
            *(float2*)(C + (row0 + 8) * N + col) = make_float2(acc[mt][nt][2], acc[mt][nt][3]);
        }
    }
}

// ---------------------------------------------------------------------------
// RoPE + split: reads g_qkv, rotates q (scaled) and k, writes bf16 hi/lo in
// flash layout [bh][S][64].
// ---------------------------------------------------------------------------
__global__ void ropesplit_k(const int* __restrict__ pos)
{
    int idx = blockIdx.x * blockDim.x + threadIdx.x;
    const int total = ROWS * HH * 2 * 32;
    if (idx >= total) return;
    int i = idx & 31;
    int rest = idx >> 5;
    int comp = rest & 1; rest >>= 1;   // 0 = q, 1 = k
    int h = rest & 15;
    int row = rest >> 4;
    int b = row >> 11;                 // / SS
    int s = row & (SS - 1);
    int bh = b * HH + h;

    float p = (float)pos[row];
    float inv = powf(10000.0f, -(float)i * (1.0f / 32.0f));
    float sn, cs;
    sincosf(p * inv, &sn, &cs);

    const float* base = g_qkv + (size_t)row * (3 * DD) + h * TRIPLE + comp * HD;
    float x1 = base[i];
    float x2 = base[i + 32];
    float o1 = x1 * cs - x2 * sn;
    float o2 = x1 * sn + x2 * cs;
    if (comp == 0) { o1 *= 0.125f; o2 *= 0.125f; }

    __nv_bfloat16* dh = (comp ? g_khi : g_qhi) + ((size_t)bh * SS + s) * HD;
    __nv_bfloat16* dl = (comp ? g_klo : g_qlo) + ((size_t)bh * SS + s) * HD;
    __nv_bfloat16 h1 = __float2bfloat16_rn(o1);
    dh[i] = h1;
    dl[i] = __float2bfloat16_rn(o1 - __bfloat162float(h1));
    __nv_bfloat16 h2 = __float2bfloat16_rn(o2);
    dh[i + 32] = h2;
    dl[i + 32] = __float2bfloat16_rn(o2 - __bfloat162float(h2));
}

// ---------------------------------------------------------------------------
// V transpose + split: g_qkv v-part -> g_vth/g_vtl [bh][64][S]
// ---------------------------------------------------------------------------
__global__ __launch_bounds__(256) void vsplit_k()
{
    __shared__ float tile[64][65];
    const int bh = blockIdx.x;
    const int b = bh >> 4, h = bh & 15;
    const int s0 = blockIdx.y * 64;
    const int t = threadIdx.x;
#pragma unroll
    for (int i = 0; i < 16; i++) {
        int u = t + i * 256;
        int sl = u >> 6, d = u & 63;
        tile[sl][d] = g_qkv[(size_t)(b * SS + s0 + sl) * (3 * DD) + h * TRIPLE + 2 * HD + d];
    }
    __syncthreads();
#pragma unroll
    for (int i = 0; i < 16; i++) {
        int u = t + i * 256;
        int dl = u >> 6, sl = u & 63;
        float v = tile[sl][dl];
        __nv_bfloat16 hh = __float2bfloat16_rn(v);
        size_t o = ((size_t)bh * HD + dl) * SS + s0 + sl;
        g_vth[o] = hh;
        g_vtl[o] = __float2bfloat16_rn(v - __bfloat162float(hh));
    }
}

// ---------------------------------------------------------------------------
// HMMA causal flash attention (bf16 3-term core).
// Epilogue writes fp16 hi/lo (chi/clo) for the fp16 output projection.
// ---------------------------------------------------------------------------
#define FQ 128
#define FKT 64
#define FSQH 0
#define FSQL 16384
#define FSKV 32768
#define FBUF 32768
#define FLASH_SMEM 98304

__device__ __forceinline__ uint32_t fsw(int r, int c) {
    return (uint32_t)((r << 7) + (((c ^ (r & 7))) << 4));
}

__global__ __launch_bounds__(256) void flashmma_k()
{
    extern __shared__ char sm[];
    const uint32_t sb = smem_to_u32(sm);
    const int t = threadIdx.x, lane = t & 31, w = t >> 5;
    const int idx = lane & 7, sel = lane >> 3;
    const int bh = blockIdx.y, b = bh >> 4, h = bh & 15;
    const int qt = (int)gridDim.x - 1 - (int)blockIdx.x;   // heavy tiles first
    const int q0 = qt * FQ;
    const int qw = q0 + w * 16;
    const int ntiles = q0 / FKT + 2;

    // Q tile cp.async (hi/lo)
    {
        const __nv_bfloat16* s0 = g_qhi + ((size_t)bh * SS + q0) * HD;
        const __nv_bfloat16* s1 = g_qlo + ((size_t)bh * SS + q0) * HD;
#pragma unroll
        for (int i = 0; i < 4; i++) {
            int u = t + i * 256; int r = u >> 3, c = u & 7;
            CP_ASYNC16(sb + FSQH + fsw(r, c), s0 + (size_t)r * HD + c * 8);
        }
#pragma unroll
        for (int i = 0; i < 4; i++) {
            int u = t + i * 256; int r = u >> 3, c = u & 7;
            CP_ASYNC16(sb + FSQL + fsw(r, c), s1 + (size_t)r * HD + c * 8);
        }
        CP_COMMIT();
    }

    auto ld_kv = [&](int ct) {
        const int k0 = ct * FKT;
        const uint32_t bd = sb + FSKV + (ct & 1) * FBUF;
        const __nv_bfloat16* sk0 = g_khi + ((size_t)bh * SS + k0) * HD;
        const __nv_bfloat16* sk1 = g_klo + ((size_t)bh * SS + k0) * HD;
#pragma unroll
        for (int i = 0; i < 2; i++) {
            int u = t + i * 256; int r = u >> 3, c = u & 7;
            CP_ASYNC16(bd + fsw(r, c), sk0 + (size_t)r * HD + c * 8);
            CP_ASYNC16(bd + 8192 + fsw(r, c), sk1 + (size_t)r * HD + c * 8);
        }
        const __nv_bfloat16* sv0 = g_vth + (size_t)bh * HD * SS + k0;
        const __nv_bfloat16* sv1 = g_vtl + (size_t)bh * HD * SS + k0;
#pragma unroll
        for (int i = 0; i < 2; i++) {
            int u = t + i * 256; int r = u >> 3, c = u & 7;
            CP_ASYNC16(bd + 16384 + fsw(r, c), sv0 + (size_t)r * SS + c * 8);
            CP_ASYNC16(bd + 24576 + fsw(r, c), sv1 + (size_t)r * SS + c * 8);
        }
        CP_COMMIT();
    };

    ld_kv(0);
    CP_WAIT0();
    __syncthreads();

    // Q fragments (resident): 4 k16 chunks, hi+lo
    uint32_t qhf[4][4], qlf[4][4];
#pragma unroll
    for (int j = 0; j < 4; j++) {
        int row = w * 16 + ((sel & 1) << 3) + idx;
        int ch = 2 * j + (sel >> 1);
        ldsm4(qhf[j], sb + FSQH + fsw(row, ch));
        ldsm4(qlf[j], sb + FSQL + fsw(row, ch));
    }

    float o[8][4];
#pragma unroll
    for (int nt = 0; nt < 8; nt++)
#pragma unroll
        for (int i = 0; i < 4; i++) o[nt][i] = 0.f;
    float m0 = -INFINITY, m1 = -INFINITY, l0 = 0.f, l1 = 0.f;
    const int r = lane >> 2, cb = (lane & 3) * 2;

    for (int c = 0; c < ntiles; c++) {
        if (c + 1 < ntiles) ld_kv(c + 1);
        const int k0 = c * FKT;
        const uint32_t kb = sb + FSKV + (c & 1) * FBUF;

        if (k0 <= qw + 15) {
            float s[8][4];
#pragma unroll
            for (int nt = 0; nt < 8; nt++)
#pragma unroll
                for (int i = 0; i < 4; i++) s[nt][i] = 0.f;

            // S = Q K^T (3-term)
#pragma unroll
            for (int j = 0; j < 4; j++) {
                const int krow = ((sel >> 1) << 3) + idx;
                const int kch = 2 * j + (sel & 1);
#pragma unroll
                for (int np = 0; np < 4; np++) {
                    uint32_t th[4], tl[4];
                    ldsm4(th, kb + fsw(np * 16 + krow, kch));
                    ldsm4(tl, kb + 8192 + fsw(np * 16 + krow, kch));
                    uint32_t b0h[2] = { th[0], th[1] }, b1h[2] = { th[2], th[3] };
                    uint32_t b0l[2] = { tl[0], tl[1] }, b1l[2] = { tl[2], tl[3] };
                    mma16816(s[2 * np],     qhf[j], b0h);
                    mma16816(s[2 * np],     qhf[j], b0l);
                    mma16816(s[2 * np],     qlf[j], b0h);
                    mma16816(s[2 * np + 1], qhf[j], b1h);
                    mma16816(s[2 * np + 1], qhf[j], b1l);
                    mma16816(s[2 * np + 1], qlf[j], b1h);
                }
            }
            // causal mask
            if (k0 + FKT - 1 > qw) {
                const int row0 = qw + r, row1 = row0 + 8;
#pragma unroll
                for (int nt = 0; nt < 8; nt++) {
                    int c0 = k0 + nt * 8 + cb;
                    if (c0 > row0)     s[nt][0] = -INFINITY;
                    if (c0 + 1 > row0) s[nt][1] = -INFINITY;
                    if (c0 > row1)     s[nt][2] = -INFINITY;
                    if (c0 + 1 > row1) s[nt][3] = -INFINITY;
                }
            }
            // online softmax
            float mx0 = s[0][0], mx1 = s[0][2];
#pragma unroll
            for (int nt = 0; nt < 8; nt++) {
                mx0 = fmaxf(mx0, fmaxf(s[nt][0], s[nt][1]));
                mx1 = fmaxf(mx1, fmaxf(s[nt][2], s[nt][3]));
            }
            mx0 = fmaxf(mx0, __shfl_xor_sync(0xffffffffu, mx0, 1));
            mx0 = fmaxf(mx0, __shfl_xor_sync(0xffffffffu, mx0, 2));
            mx1 = fmaxf(mx1, __shfl_xor_sync(0xffffffffu, mx1, 1));
            mx1 = fmaxf(mx1, __shfl_xor_sync(0xffffffffu, mx1, 2));
            float mn0 = fmaxf(m0, mx0), mn1 = fmaxf(m1, mx1);
            float sc0 = __expf(m0 - mn0), sc1 = __expf(m1 - mn1);
            float rs0 = 0.f, rs1 = 0.f;
#pragma unroll
            for (int nt = 0; nt < 8; nt++) {
                s[nt][0] = __expf(s[nt][0] - mn0); rs0 += s[nt][0];
                s[nt][1] = __expf(s[nt][1] - mn0); rs0 += s[nt][1];
                s[nt][2] = __expf(s[nt][2] - mn1); rs1 += s[nt][2];
                s[nt][3] = __expf(s[nt][3] - mn1); rs1 += s[nt][3];
            }
            rs0 += __shfl_xor_sync(0xffffffffu, rs0, 1);
            rs0 += __shfl_xor_sync(0xffffffffu, rs0, 2);
            rs1 += __shfl_xor_sync(0xffffffffu, rs1, 1);
            rs1 += __shfl_xor_sync(0xffffffffu, rs1, 2);
            m0 = mn0; m1 = mn1;
            l0 = l0 * sc0 + rs0; l1 = l1 * sc1 + rs1;
#pragma unroll
            for (int nt = 0; nt < 8; nt++) {
                o[nt][0] *= sc0; o[nt][1] *= sc0;
                o[nt][2] *= sc1; o[nt][3] *= sc1;
            }
            // O += P V (3-term); P A-fragments from S fragments
#pragma unroll
            for (int j = 0; j < 4; j++) {
                uint32_t pah[4], pal[4];
                {
                    uint32_t p0; float r0, r1;
                    p0 = packbf(s[2 * j][0], s[2 * j][1]);
                    r0 = s[2 * j][0] - __uint_as_float(p0 << 16);
                    r1 = s[2 * j][1] - __uint_as_float(p0 & 0xFFFF0000u);
                    pah[0] = p0; pal[0] = packbf(r0, r1);
                    p0 = packbf(s[2 * j][2], s[2 * j][3]);
                    r0 = s[2 * j][2] - __uint_as_float(p0 << 16);
                    r1 = s[2 * j][3] - __uint_as_float(p0 & 0xFFFF0000u);
                    pah[1] = p0; pal[1] = packbf(r0, r1);
                    p0 = packbf(s[2 * j + 1][0], s[2 * j + 1][1]);
                    r0 = s[2 * j + 1][0] - __uint_as_float(p0 << 16);
                    r1 = s[2 * j + 1][1] - __uint_as_float(p0 & 0xFFFF0000u);
                    pah[2] = p0; pal[2] = packbf(r0, r1);
                    p0 = packbf(s[2 * j + 1][2], s[2 * j + 1][3]);
                    r0 = s[2 * j + 1][2] - __uint_as_float(p0 << 16);
                    r1 = s[2 * j + 1][3] - __uint_as_float(p0 & 0xFFFF0000u);
                    pah[3] = p0; pal[3] = packbf(r0, r1);
                }
                const int vrow = ((sel >> 1) << 3) + idx;
                const int vch = 2 * j + (sel & 1);
#pragma unroll
                for (int np = 0; np < 4; np++) {
                    uint32_t th[4], tl[4];
                    ldsm4(th, kb + 16384 + fsw(np * 16 + vrow, vch));
                    ldsm4(tl, kb + 24576 + fsw(np * 16 + vrow, vch));
                    uint32_t b0h[2] = { th[0], th[1] }, b1h[2] = { th[2], th[3] };
                    uint32_t b0l[2] = { tl[0], tl[1] }, b1l[2] = { tl[2], tl[3] };
                    mma16816(o[2 * np],     pah, b0h);
                    mma16816(o[2 * np],     pah, b0l);
                    mma16816(o[2 * np],     pal, b0h);
                    mma16816(o[2 * np + 1], pah, b1h);
                    mma16816(o[2 * np + 1], pah, b1l);
                    mma16816(o[2 * np + 1], pal, b1h);
                }
            }
        }
        __syncthreads();
        if (c + 1 < ntiles) { CP_WAIT0(); __syncthreads(); }
    }

    // epilogue: normalize, split to fp16 hi/lo, write chi/clo [row][h*64+d]
    float i0 = 1.f / l0, i1 = 1.f / l1;
    const size_t row0 = (size_t)b * SS + qw + r;
    const size_t row1 = row0 + 8;
#pragma unroll
    for (int nt = 0; nt < 8; nt++) {
        int col = h * HD + nt * 8 + cb;
        float a0 = o[nt][0] * i0, a1 = o[nt][1] * i0;
        uint32_t p = packh(a0, a1);
        __half2 hp = *(__half2*)&p;
        float r0 = a0 - __half2float(__low2half(hp));
        float r1 = a1 - __half2float(__high2half(hp));
        *(uint32_t*)(g_chi + row0 * DD + col) = p;
        *(uint32_t*)(g_clo + row0 * DD + col) = packh(r0, r1);
        a0 = o[nt][2] * i1; a1 = o[nt][3] * i1;
        p = packh(a0, a1);
        hp = *(__half2*)&p;
        r0 = a0 - __half2float(__low2half(hp));
        r1 = a1 - __half2float(__high2half(hp));
        *(uint32_t*)(g_chi + row1 * DD + col) = p;
        *(uint32_t*)(g_clo + row1 * DD + col) = packh(r0, r1);
    }
}

// ---------------------------------------------------------------------------
// Launch
// Inputs: 0=inputs f32[B,S,D], 1=segment_positions i32[B,S], 2=mask (unused),
// 3=W_in f32[D,3D], 4=W_out f32[D,D]. Output: f32[B,S,D].
// ---------------------------------------------------------------------------
extern "C" void kernel_launch(void* const* d_in, const int* in_sizes, int n_in,
                              void* d_out, int out_size)
{
    const float* x    = (const float*)d_in[0];
    const int*   pos  = (const int*)d_in[1];
    const float* Win  = (const float*)d_in[3];
    const float* Wout = (const float*)d_in[4];
    float* out = (float*)d_out;

    float* qkv;
    __half *ahi, *alo, *chi, *clo, *wT, *oT;
    cudaGetSymbolAddress((void**)&qkv, g_qkv);
    cudaGetSymbolAddress((void**)&ahi, g_ahi);
    cudaGetSymbolAddress((void**)&alo, g_alo);
    cudaGetSymbolAddress((void**)&chi, g_chi);
    cudaGetSymbolAddress((void**)&clo, g_clo);
    cudaGetSymbolAddress((void**)&wT, g_wT);
    cudaGetSymbolAddress((void**)&oT, g_oT);

    cudaFuncSetAttribute(gemm_hmma_k,
                         cudaFuncAttributeMaxDynamicSharedMemorySize, GEMM_SMEM_SZ);
    cudaFuncSetAttribute(flashmma_k,
                         cudaFuncAttributeMaxDynamicSharedMemorySize, FLASH_SMEM);

    // 0) split inputs (fp16 hi/lo), transpose+round weights (fp16)
    {
        int n = ROWS * DD;
        split_k<<<(n + 255) / 256, 256>>>(x, ahi, alo, n);
    }
    tsplit_k<<<dim3(3 * DD / 32, DD / 32), 256>>>(Win, wT, DD, 3 * DD);
    tsplit_k<<<dim3(DD / 32, DD / 32), 256>>>(Wout, oT, DD, DD);

    // 1) QKV projection via fp16 HMMA (2-term)
    gemm_hmma_k<<<dim3(3 * DD / 128, ROWS / 128), 256, GEMM_SMEM_SZ>>>(
        ahi, alo, wT, qkv, 3 * DD);

    // 2) RoPE + bf16 hi/lo split into flash layouts; V transpose+split
    {
        int nrope = ROWS * HH * 2 * 32;
        ropesplit_k<<<(nrope + 255) / 256, 256>>>(pos);
    }
    vsplit_k<<<dim3(BB * HH, SS / 64), 256>>>();

    // 3) HMMA causal flash attention (bf16 3-term; writes fp16 chi/clo)
    flashmma_k<<<dim3(SS / FQ, BB * HH), 256, FLASH_SMEM>>>();

    // 4) Output projection via fp16 HMMA (2-term)
    gemm_hmma_k<<<dim3(DD / 128, ROWS / 128), 256, GEMM_SMEM_SZ>>>(
        chi, clo, oT, out, DD);
}

// round 8
// speedup vs baseline: 5.2658x; 1.1929x over previous
#include <cuda_runtime.h>
#include <cuda_bf16.h>
#include <cuda_fp16.h>
#include <math.h>
#include <stdint.h>

#define BB 2
#define SS 2048
#define DD 1024
#define HH 16
#define HD 64
#define ROWS (BB*SS)      // 4096
#define TRIPLE (3*HD)     // 192 floats per (row, head)
#define GK 1024           // GEMM K dim (fixed)

// ---------------------------------------------------------------------------
// Scratch (static device globals; no allocation at runtime)
// ---------------------------------------------------------------------------
__device__ float g_qkv[(size_t)ROWS * 3 * DD];        // [ROWS][H][192] fp32
__device__ __half g_ah[(size_t)ROWS * DD];            // inputs fp16 [row][K]
__device__ __half g_ch[(size_t)ROWS * DD];            // attn out fp16 [row][D]
__device__ __half g_wT[(size_t)3 * DD * DD];          // W_in^T fp16 [3072][1024]
__device__ __half g_oT[(size_t)DD * DD];              // W_out^T fp16 [1024][1024]
// flash operands (bf16 3-term path): Q,K [bh][S][64]; V^T [bh][64][S]
__device__ __nv_bfloat16 g_qhi[(size_t)BB * HH * SS * HD];
__device__ __nv_bfloat16 g_qlo[(size_t)BB * HH * SS * HD];
__device__ __nv_bfloat16 g_khi[(size_t)BB * HH * SS * HD];
__device__ __nv_bfloat16 g_klo[(size_t)BB * HH * SS * HD];
__device__ __nv_bfloat16 g_vth[(size_t)BB * HH * HD * SS];
__device__ __nv_bfloat16 g_vtl[(size_t)BB * HH * HD * SS];

// ---------------------------------------------------------------------------
// PTX helpers (portable: mma.sync / ldmatrix / cp.async — no arch-'a' features)
// ---------------------------------------------------------------------------
__device__ __forceinline__ uint32_t smem_to_u32(const void* smem_ptr) {
    uint32_t addr;
    asm("{ .reg .u64 tmp; cvta.to.shared.u64 tmp, %1; cvt.u32.u64 %0, tmp; }"
        : "=r"(addr) : "l"(smem_ptr));
    return addr;
}
__device__ __forceinline__ void ldsm4(uint32_t* r, uint32_t addr) {
    asm volatile("ldmatrix.sync.aligned.m8n8.x4.shared.b16 {%0,%1,%2,%3}, [%4];"
                 : "=r"(r[0]), "=r"(r[1]), "=r"(r[2]), "=r"(r[3]) : "r"(addr));
}
__device__ __forceinline__ void mma16816(float* c, const uint32_t* a, const uint32_t* b) {
    asm volatile(
        "mma.sync.aligned.m16n8k16.row.col.f32.bf16.bf16.f32 "
        "{%0,%1,%2,%3}, {%4,%5,%6,%7}, {%8,%9}, {%0,%1,%2,%3};"
        : "+f"(c[0]), "+f"(c[1]), "+f"(c[2]), "+f"(c[3])
        : "r"(a[0]), "r"(a[1]), "r"(a[2]), "r"(a[3]), "r"(b[0]), "r"(b[1]));
}
__device__ __forceinline__ void mma16816h(float* c, const uint32_t* a, const uint32_t* b) {
    asm volatile(
        "mma.sync.aligned.m16n8k16.row.col.f32.f16.f16.f32 "
        "{%0,%1,%2,%3}, {%4,%5,%6,%7}, {%8,%9}, {%0,%1,%2,%3};"
        : "+f"(c[0]), "+f"(c[1]), "+f"(c[2]), "+f"(c[3])
        : "r"(a[0]), "r"(a[1]), "r"(a[2]), "r"(a[3]), "r"(b[0]), "r"(b[1]));
}
__device__ __forceinline__ uint32_t packbf(float lo, float hi) {
    uint32_t d;
    asm("cvt.rn.bf16x2.f32 %0, %1, %2;" : "=r"(d) : "f"(hi), "f"(lo));
    return d;
}
__device__ __forceinline__ uint32_t packh(float lo, float hi) {
    __half2 h = __floats2half2_rn(lo, hi);
    return *(uint32_t*)&h;
}
#define CP_ASYNC16(sm_u32, gptr) \
    asm volatile("cp.async.cg.shared.global [%0], [%1], 16;" :: "r"(sm_u32), "l"(gptr))
#define CP_COMMIT() asm volatile("cp.async.commit_group;" ::: "memory")
#define CP_WAIT1()  asm volatile("cp.async.wait_group 1;" ::: "memory")
#define CP_WAIT0()  asm volatile("cp.async.wait_group 0;" ::: "memory")

// ---------------------------------------------------------------------------
// Convert kernels
// ---------------------------------------------------------------------------
__global__ void cvt_k(const float* __restrict__ in,
                      __half* __restrict__ out, int n)
{
    int i = blockIdx.x * blockDim.x + threadIdx.x;
    if (i >= n) return;
    out[i] = __float2half_rn(in[i]);
}

// Transpose + round: in [K][N] fp32 -> outT [N][K] fp16
__global__ __launch_bounds__(256) void tsplit_k(const float* __restrict__ in,
                                                __half* __restrict__ outT,
                                                int K, int N)
{
    __shared__ float tile[32][33];
    const int tx = threadIdx.x & 31;
    const int ty = threadIdx.x >> 5;       // 0..7
    const int n0 = blockIdx.x * 32;
    const int k0 = blockIdx.y * 32;
#pragma unroll
    for (int i = 0; i < 4; i++) {
        int kk = ty + 8 * i;
        tile[kk][tx] = in[(size_t)(k0 + kk) * N + n0 + tx];
    }
    __syncthreads();
#pragma unroll
    for (int i = 0; i < 4; i++) {
        int nn = ty + 8 * i;
        outT[(size_t)(n0 + nn) * K + k0 + tx] = __float2half_rn(tile[tx][nn]);
    }
}

// ---------------------------------------------------------------------------
// HMMA fp16 single-term GEMM: C[M,N] = A[M,K] * B^T  (A, B fp16; B [N][K])
// 128x128 block, 8 warps (warp tile 64x32), KC=32, 3-stage cp.async pipeline,
// one __syncthreads per k-iteration.
// ---------------------------------------------------------------------------
#define KC 32
#define NKC (GK / KC)            // 32
#define ROWB 80                  // 32 fp16 = 64B data + 16B pad
#define TILE_SB (128 * ROWB)     // 10240
#define STAGE_SB (2 * TILE_SB)   // A, B = 20480
#define NSTG 3
#define GEMM_SMEM_SZ (NSTG * STAGE_SB)  // 61440

__global__ __launch_bounds__(256) void gemm_hmma_k(
    const __half* __restrict__ ah,
    const __half* __restrict__ bT,
    float* __restrict__ C, int N)
{
    extern __shared__ char sm[];
    const uint32_t sb = smem_to_u32(sm);
    const int t = threadIdx.x;
    const int lane = t & 31;
    const int wid = t >> 5;
    const int wm = wid & 1;
    const int wn = wid >> 1;
    const size_t arow0 = (size_t)blockIdx.y * 128;
    const size_t brow0 = (size_t)blockIdx.x * 128;

    const __half* gsrc[2] = { ah + arow0 * GK, bT + brow0 * GK };

    auto issue_stage = [&](int c) {
        const uint32_t st = sb + (uint32_t)(c % NSTG) * STAGE_SB;
        const size_t k0 = (size_t)c * KC;
#pragma unroll
        for (int comp = 0; comp < 2; comp++) {
#pragma unroll
            for (int i = 0; i < 2; i++) {
                int u = t + i * 256;
                int r = u >> 2, ch = u & 3;
                const void* g = gsrc[comp] + (size_t)r * GK + k0 + ch * 8;
                CP_ASYNC16(st + comp * TILE_SB + r * ROWB + ch * 16, g);
            }
        }
    };

    float acc[4][4][4];
#pragma unroll
    for (int mt = 0; mt < 4; mt++)
#pragma unroll
        for (int nt = 0; nt < 4; nt++)
#pragma unroll
            for (int i = 0; i < 4; i++) acc[mt][nt][i] = 0.f;

    issue_stage(0); CP_COMMIT();
    issue_stage(1); CP_COMMIT();
    CP_WAIT1();
    __syncthreads();

    const int idx = lane & 7;
    const int sel = lane >> 3;

    for (int c = 0; c < NKC; c++) {
        if (c + 2 < NKC) issue_stage(c + 2);
        CP_COMMIT();                         // one group per iteration, always
        const uint32_t st = sb + (uint32_t)(c % NSTG) * STAGE_SB;

#pragma unroll
        for (int j = 0; j < 2; j++) {
            uint32_t af[4][4], bf[4][2];
            const uint32_t acol = (uint32_t)((2 * j + (sel >> 1)) << 4);
#pragma unroll
            for (int mt = 0; mt < 4; mt++) {
                uint32_t ra = (uint32_t)(wm * 64 + mt * 16 + ((sel & 1) << 3) + idx);
                ldsm4(af[mt], st + ra * ROWB + acol);
            }
            {
                const uint32_t bcol = (uint32_t)((2 * j + (sel & 1)) << 4);
                uint32_t rb = (uint32_t)(wn * 32 + ((sel >> 1) << 3) + idx);
                uint32_t bd = st + TILE_SB + rb * ROWB + bcol;
                uint32_t tmp[4];
                ldsm4(tmp, bd);
                bf[0][0] = tmp[0]; bf[0][1] = tmp[1];
                bf[1][0] = tmp[2]; bf[1][1] = tmp[3];
                ldsm4(tmp, bd + 16 * ROWB);
                bf[2][0] = tmp[0]; bf[2][1] = tmp[1];
                bf[3][0] = tmp[2]; bf[3][1] = tmp[3];
            }
#pragma unroll
            for (int mt = 0; mt < 4; mt++)
#pragma unroll
                for (int nt = 0; nt < 4; nt++)
                    mma16816h(acc[mt][nt], af[mt], bf[nt]);
        }
        CP_WAIT1();                          // next stage resident
        __syncthreads();
    }

    const int g = lane >> 2, tg = lane & 3;
#pragma unroll
    for (int mt = 0; mt < 4; mt++) {
        size_t row0 = arow0 + wm * 64 + mt * 16 + g;
#pragma unroll
        for (int nt = 0; nt < 4; nt++) {
            size_t col = brow0 + wn * 32 + nt * 8 + tg * 2;
            *(float2*)(C + row0 * N + col) = make_float2(acc[mt][nt][0], acc[mt][nt][1]);
            *(float2*)(C + (row0 + 8) * N + col) = make_float2(acc[mt][nt][2], acc[mt][nt][3]);
        }
    }
}

// ---------------------------------------------------------------------------
// RoPE + split: reads g_qkv, rotates q (scaled) and k, writes bf16 hi/lo in
// flash layout [bh][S][64].
// ---------------------------------------------------------------------------
__global__ void ropesplit_k(const int* __restrict__ pos)
{
    int idx = blockIdx.x * blockDim.x + threadIdx.x;
    const int total = ROWS * HH * 2 * 32;
    if (idx >= total) return;
    int i = idx & 31;
    int rest = idx >> 5;
    int comp = rest & 1; rest >>= 1;   // 0 = q, 1 = k
    int h = rest & 15;
    int row = rest >> 4;
    int b = row >> 11;                 // / SS
    int s = row & (SS - 1);
    int bh = b * HH + h;

    float p = (float)pos[row];
    float inv = powf(10000.0f, -(float)i * (1.0f / 32.0f));
    float sn, cs;
    sincosf(p * inv, &sn, &cs);

    const float* base = g_qkv + (size_t)row * (3 * DD) + h * TRIPLE + comp * HD;
    float x1 = base[i];
    float x2 = base[i + 32];
    float o1 = x1 * cs - x2 * sn;
    float o2 = x1 * sn + x2 * cs;
    if (comp == 0) { o1 *= 0.125f; o2 *= 0.125f; }

    __nv_bfloat16* dh = (comp ? g_khi : g_qhi) + ((size_t)bh * SS + s) * HD;
    __nv_bfloat16* dl = (comp ? g_klo : g_qlo) + ((size_t)bh * SS + s) * HD;
    __nv_bfloat16 h1 = __float2bfloat16_rn(o1);
    dh[i] = h1;
    dl[i] = __float2bfloat16_rn(o1 - __bfloat162float(h1));
    __nv_bfloat16 h2 = __float2bfloat16_rn(o2);
    dh[i + 32] = h2;
    dl[i + 32] = __float2bfloat16_rn(o2 - __bfloat162float(h2));
}

// ---------------------------------------------------------------------------
// V transpose + split: g_qkv v-part -> g_vth/g_vtl [bh][64][S]
// ---------------------------------------------------------------------------
__global__ __launch_bounds__(256) void vsplit_k()
{
    __shared__ float tile[64][65];
    const int bh = blockIdx.x;
    const int b = bh >> 4, h = bh & 15;
    const int s0 = blockIdx.y * 64;
    const int t = threadIdx.x;
#pragma unroll
    for (int i = 0; i < 16; i++) {
        int u = t + i * 256;
        int sl = u >> 6, d = u & 63;
        tile[sl][d] = g_qkv[(size_t)(b * SS + s0 + sl) * (3 * DD) + h * TRIPLE + 2 * HD + d];
    }
    __syncthreads();
#pragma unroll
    for (int i = 0; i < 16; i++) {
        int u = t + i * 256;
        int dl = u >> 6, sl = u & 63;
        float v = tile[sl][dl];
        __nv_bfloat16 hh = __float2bfloat16_rn(v);
        size_t o = ((size_t)bh * HD + dl) * SS + s0 + sl;
        g_vth[o] = hh;
        g_vtl[o] = __float2bfloat16_rn(v - __bfloat162float(hh));
    }
}

// ---------------------------------------------------------------------------
// HMMA causal flash attention (bf16 3-term core).
// Epilogue writes single fp16 (g_ch) for the fp16 output projection.
// ---------------------------------------------------------------------------
#define FQ 128
#define FKT 64
#define FSQH 0
#define FSQL 16384
#define FSKV 32768
#define FBUF 32768
#define FLASH_SMEM 98304

__device__ __forceinline__ uint32_t fsw(int r, int c) {
    return (uint32_t)((r << 7) + (((c ^ (r & 7))) << 4));
}

__global__ __launch_bounds__(256) void flashmma_k()
{
    extern __shared__ char sm[];
    const uint32_t sb = smem_to_u32(sm);
    const int t = threadIdx.x, lane = t & 31, w = t >> 5;
    const int idx = lane & 7, sel = lane >> 3;
    const int bh = blockIdx.y, b = bh >> 4, h = bh & 15;
    const int qt = (int)gridDim.x - 1 - (int)blockIdx.x;   // heavy tiles first
    const int q0 = qt * FQ;
    const int qw = q0 + w * 16;
    const int ntiles = q0 / FKT + 2;

    // Q tile cp.async (hi/lo)
    {
        const __nv_bfloat16* s0 = g_qhi + ((size_t)bh * SS + q0) * HD;
        const __nv_bfloat16* s1 = g_qlo + ((size_t)bh * SS + q0) * HD;
#pragma unroll
        for (int i = 0; i < 4; i++) {
            int u = t + i * 256; int r = u >> 3, c = u & 7;
            CP_ASYNC16(sb + FSQH + fsw(r, c), s0 + (size_t)r * HD + c * 8);
        }
#pragma unroll
        for (int i = 0; i < 4; i++) {
            int u = t + i * 256; int r = u >> 3, c = u & 7;
            CP_ASYNC16(sb + FSQL + fsw(r, c), s1 + (size_t)r * HD + c * 8);
        }
        CP_COMMIT();
    }

    auto ld_kv = [&](int ct) {
        const int k0 = ct * FKT;
        const uint32_t bd = sb + FSKV + (ct & 1) * FBUF;
        const __nv_bfloat16* sk0 = g_khi + ((size_t)bh * SS + k0) * HD;
        const __nv_bfloat16* sk1 = g_klo + ((size_t)bh * SS + k0) * HD;
#pragma unroll
        for (int i = 0; i < 2; i++) {
            int u = t + i * 256; int r = u >> 3, c = u & 7;
            CP_ASYNC16(bd + fsw(r, c), sk0 + (size_t)r * HD + c * 8);
            CP_ASYNC16(bd + 8192 + fsw(r, c), sk1 + (size_t)r * HD + c * 8);
        }
        const __nv_bfloat16* sv0 = g_vth + (size_t)bh * HD * SS + k0;
        const __nv_bfloat16* sv1 = g_vtl + (size_t)bh * HD * SS + k0;
#pragma unroll
        for (int i = 0; i < 2; i++) {
            int u = t + i * 256; int r = u >> 3, c = u & 7;
            CP_ASYNC16(bd + 16384 + fsw(r, c), sv0 + (size_t)r * SS + c * 8);
            CP_ASYNC16(bd + 24576 + fsw(r, c), sv1 + (size_t)r * SS + c * 8);
        }
        CP_COMMIT();
    };

    ld_kv(0);
    CP_WAIT0();
    __syncthreads();

    // Q fragments (resident): 4 k16 chunks, hi+lo
    uint32_t qhf[4][4], qlf[4][4];
#pragma unroll
    for (int j = 0; j < 4; j++) {
        int row = w * 16 + ((sel & 1) << 3) + idx;
        int ch = 2 * j + (sel >> 1);
        ldsm4(qhf[j], sb + FSQH + fsw(row, ch));
        ldsm4(qlf[j], sb + FSQL + fsw(row, ch));
    }

    float o[8][4];
#pragma unroll
    for (int nt = 0; nt < 8; nt++)
#pragma unroll
        for (int i = 0; i < 4; i++) o[nt][i] = 0.f;
    float m0 = -INFINITY, m1 = -INFINITY, l0 = 0.f, l1 = 0.f;
    const int r = lane >> 2, cb = (lane & 3) * 2;

    for (int c = 0; c < ntiles; c++) {
        if (c + 1 < ntiles) ld_kv(c + 1);
        const int k0 = c * FKT;
        const uint32_t kb = sb + FSKV + (c & 1) * FBUF;

        if (k0 <= qw + 15) {
            float s[8][4];
#pragma unroll
            for (int nt = 0; nt < 8; nt++)
#pragma unroll
                for (int i = 0; i < 4; i++) s[nt][i] = 0.f;

            // S = Q K^T (3-term)
#pragma unroll
            for (int j = 0; j < 4; j++) {
                const int krow = ((sel >> 1) << 3) + idx;
                const int kch = 2 * j + (sel & 1);
#pragma unroll
                for (int np = 0; np < 4; np++) {
                    uint32_t th[4], tl[4];
                    ldsm4(th, kb + fsw(np * 16 + krow, kch));
                    ldsm4(tl, kb + 8192 + fsw(np * 16 + krow, kch));
                    uint32_t b0h[2] = { th[0], th[1] }, b1h[2] = { th[2], th[3] };
                    uint32_t b0l[2] = { tl[0], tl[1] }, b1l[2] = { tl[2], tl[3] };
                    mma16816(s[2 * np],     qhf[j], b0h);
                    mma16816(s[2 * np],     qhf[j], b0l);
                    mma16816(s[2 * np],     qlf[j], b0h);
                    mma16816(s[2 * np + 1], qhf[j], b1h);
                    mma16816(s[2 * np + 1], qhf[j], b1l);
                    mma16816(s[2 * np + 1], qlf[j], b1h);
                }
            }
            // causal mask
            if (k0 + FKT - 1 > qw) {
                const int row0 = qw + r, row1 = row0 + 8;
#pragma unroll
                for (int nt = 0; nt < 8; nt++) {
                    int c0 = k0 + nt * 8 + cb;
                    if (c0 > row0)     s[nt][0] = -INFINITY;
                    if (c0 + 1 > row0) s[nt][1] = -INFINITY;
                    if (c0 > row1)     s[nt][2] = -INFINITY;
                    if (c0 + 1 > row1) s[nt][3] = -INFINITY;
                }
            }
            // online softmax
            float mx0 = s[0][0], mx1 = s[0][2];
#pragma unroll
            for (int nt = 0; nt < 8; nt++) {
                mx0 = fmaxf(mx0, fmaxf(s[nt][0], s[nt][1]));
                mx1 = fmaxf(mx1, fmaxf(s[nt][2], s[nt][3]));
            }
            mx0 = fmaxf(mx0, __shfl_xor_sync(0xffffffffu, mx0, 1));
            mx0 = fmaxf(mx0, __shfl_xor_sync(0xffffffffu, mx0, 2));
            mx1 = fmaxf(mx1, __shfl_xor_sync(0xffffffffu, mx1, 1));
            mx1 = fmaxf(mx1, __shfl_xor_sync(0xffffffffu, mx1, 2));
            float mn0 = fmaxf(m0, mx0), mn1 = fmaxf(m1, mx1);
            float sc0 = __expf(m0 - mn0), sc1 = __expf(m1 - mn1);
            float rs0 = 0.f, rs1 = 0.f;
#pragma unroll
            for (int nt = 0; nt < 8; nt++) {
                s[nt][0] = __expf(s[nt][0] - mn0); rs0 += s[nt][0];
                s[nt][1] = __expf(s[nt][1] - mn0); rs0 += s[nt][1];
                s[nt][2] = __expf(s[nt][2] - mn1); rs1 += s[nt][2];
                s[nt][3] = __expf(s[nt][3] - mn1); rs1 += s[nt][3];
            }
            rs0 += __shfl_xor_sync(0xffffffffu, rs0, 1);
            rs0 += __shfl_xor_sync(0xffffffffu, rs0, 2);
            rs1 += __shfl_xor_sync(0xffffffffu, rs1, 1);
            rs1 += __shfl_xor_sync(0xffffffffu, rs1, 2);
            m0 = mn0; m1 = mn1;
            l0 = l0 * sc0 + rs0; l1 = l1 * sc1 + rs1;
#pragma unroll
            for (int nt = 0; nt < 8; nt++) {
                o[nt][0] *= sc0; o[nt][1] *= sc0;
                o[nt][2] *= sc1; o[nt][3] *= sc1;
            }
            // O += P V (3-term); P A-fragments from S fragments
#pragma unroll
            for (int j = 0; j < 4; j++) {
                uint32_t pah[4], pal[4];
                {
                    uint32_t p0; float r0, r1;
                    p0 = packbf(s[2 * j][0], s[2 * j][1]);
                    r0 = s[2 * j][0] - __uint_as_float(p0 << 16);
                    r1 = s[2 * j][1] - __uint_as_float(p0 & 0xFFFF0000u);
                    pah[0] = p0; pal[0] = packbf(r0, r1);
                    p0 = packbf(s[2 * j][2], s[2 * j][3]);
                    r0 = s[2 * j][2] - __uint_as_float(p0 << 16);
                    r1 = s[2 * j][3] - __uint_as_float(p0 & 0xFFFF0000u);
                    pah[1] = p0; pal[1] = packbf(r0, r1);
                    p0 = packbf(s[2 * j + 1][0], s[2 * j + 1][1]);
                    r0 = s[2 * j + 1][0] - __uint_as_float(p0 << 16);
                    r1 = s[2 * j + 1][1] - __uint_as_float(p0 & 0xFFFF0000u);
                    pah[2] = p0; pal[2] = packbf(r0, r1);
                    p0 = packbf(s[2 * j + 1][2], s[2 * j + 1][3]);
                    r0 = s[2 * j + 1][2] - __uint_as_float(p0 << 16);
                    r1 = s[2 * j + 1][3] - __uint_as_float(p0 & 0xFFFF0000u);
                    pah[3] = p0; pal[3] = packbf(r0, r1);
                }
                const int vrow = ((sel >> 1) << 3) + idx;
                const int vch = 2 * j + (sel & 1);
#pragma unroll
                for (int np = 0; np < 4; np++) {
                    uint32_t th[4], tl[4];
                    ldsm4(th, kb + 16384 + fsw(np * 16 + vrow, vch));
                    ldsm4(tl, kb + 24576 + fsw(np * 16 + vrow, vch));
                    uint32_t b0h[2] = { th[0], th[1] }, b1h[2] = { th[2], th[3] };
                    uint32_t b0l[2] = { tl[0], tl[1] }, b1l[2] = { tl[2], tl[3] };
                    mma16816(o[2 * np],     pah, b0h);
                    mma16816(o[2 * np],     pah, b0l);
                    mma16816(o[2 * np],     pal, b0h);
                    mma16816(o[2 * np + 1], pah, b1h);
                    mma16816(o[2 * np + 1], pah, b1l);
                    mma16816(o[2 * np + 1], pal, b1h);
                }
            }
        }
        __syncthreads();
        if (c + 1 < ntiles) { CP_WAIT0(); __syncthreads(); }
    }

    // epilogue: normalize, round to fp16, write g_ch [row][h*64+d]
    float i0 = 1.f / l0, i1 = 1.f / l1;
    const size_t row0 = (size_t)b * SS + qw + r;
    const size_t row1 = row0 + 8;
#pragma unroll
    for (int nt = 0; nt < 8; nt++) {
        int col = h * HD + nt * 8 + cb;
        *(uint32_t*)(g_ch + row0 * DD + col) = packh(o[nt][0] * i0, o[nt][1] * i0);
        *(uint32_t*)(g_ch + row1 * DD + col) = packh(o[nt][2] * i1, o[nt][3] * i1);
    }
}

// ---------------------------------------------------------------------------
// Launch
// Inputs: 0=inputs f32[B,S,D], 1=segment_positions i32[B,S], 2=mask (unused),
// 3=W_in f32[D,3D], 4=W_out f32[D,D]. Output: f32[B,S,D].
// ---------------------------------------------------------------------------
extern "C" void kernel_launch(void* const* d_in, const int* in_sizes, int n_in,
                              void* d_out, int out_size)
{
    const float* x    = (const float*)d_in[0];
    const int*   pos  = (const int*)d_in[1];
    const float* Win  = (const float*)d_in[3];
    const float* Wout = (const float*)d_in[4];
    float* out = (float*)d_out;

    float* qkv;
    __half *ah, *ch, *wT, *oT;
    cudaGetSymbolAddress((void**)&qkv, g_qkv);
    cudaGetSymbolAddress((void**)&ah, g_ah);
    cudaGetSymbolAddress((void**)&ch, g_ch);
    cudaGetSymbolAddress((void**)&wT, g_wT);
    cudaGetSymbolAddress((void**)&oT, g_oT);

    cudaFuncSetAttribute(gemm_hmma_k,
                         cudaFuncAttributeMaxDynamicSharedMemorySize, GEMM_SMEM_SZ);
    cudaFuncSetAttribute(flashmma_k,
                         cudaFuncAttributeMaxDynamicSharedMemorySize, FLASH_SMEM);

    // 0) round inputs to fp16; transpose+round weights to fp16
    {
        int n = ROWS * DD;
        cvt_k<<<(n + 255) / 256, 256>>>(x, ah, n);
    }
    tsplit_k<<<dim3(3 * DD / 32, DD / 32), 256>>>(Win, wT, DD, 3 * DD);
    tsplit_k<<<dim3(DD / 32, DD / 32), 256>>>(Wout, oT, DD, DD);

    // 1) QKV projection via fp16 HMMA (single-term)
    gemm_hmma_k<<<dim3(3 * DD / 128, ROWS / 128), 256, GEMM_SMEM_SZ>>>(
        ah, wT, qkv, 3 * DD);

    // 2) RoPE + bf16 hi/lo split into flash layouts; V transpose+split
    {
        int nrope = ROWS * HH * 2 * 32;
        ropesplit_k<<<(nrope + 255) / 256, 256>>>(pos);
    }
    vsplit_k<<<dim3(BB * HH, SS / 64), 256>>>();

    // 3) HMMA causal flash attention (bf16 3-term; writes fp16 g_ch)
    flashmma_k<<<dim3(SS / FQ, BB * HH), 256, FLASH_SMEM>>>();

    // 4) Output projection via fp16 HMMA (single-term)
    gemm_hmma_k<<<dim3(DD / 128, ROWS / 128), 256, GEMM_SMEM_SZ>>>(
        ch, oT, out, DD);
}

// round 9
// speedup vs baseline: 7.2282x; 1.3727x over previous
#include <cuda_runtime.h>
#include <cuda_bf16.h>
#include <cuda_fp16.h>
#include <math.h>
#include <stdint.h>

#define BB 2
#define SS 2048
#define DD 1024
#define HH 16
#define HD 64
#define ROWS (BB*SS)      // 4096
#define TRIPLE (3*HD)     // 192 floats per (row, head)
#define GK 1024           // GEMM K dim (fixed)

// ---------------------------------------------------------------------------
// Scratch (static device globals; no allocation at runtime)
// ---------------------------------------------------------------------------
__device__ float g_qkv[(size_t)ROWS * 3 * DD];        // [ROWS][H][192] fp32
__device__ __half g_ah[(size_t)ROWS * DD];            // inputs fp16 [row][K]
__device__ __half g_ch[(size_t)ROWS * DD];            // attn out fp16 [row][D]
__device__ __half g_wT[(size_t)3 * DD * DD];          // W_in^T fp16 [3072][1024]
__device__ __half g_oT[(size_t)DD * DD];              // W_out^T fp16 [1024][1024]
// flash operands (fp16 single-term): Q,K [bh][S][64]; V^T [bh][64][S]
__device__ __half g_qh[(size_t)BB * HH * SS * HD];
__device__ __half g_kh[(size_t)BB * HH * SS * HD];
__device__ __half g_vt[(size_t)BB * HH * HD * SS];

// ---------------------------------------------------------------------------
// PTX helpers (portable: mma.sync / ldmatrix / cp.async — no arch-'a' features)
// ---------------------------------------------------------------------------
__device__ __forceinline__ uint32_t smem_to_u32(const void* smem_ptr) {
    uint32_t addr;
    asm("{ .reg .u64 tmp; cvta.to.shared.u64 tmp, %1; cvt.u32.u64 %0, tmp; }"
        : "=r"(addr) : "l"(smem_ptr));
    return addr;
}
__device__ __forceinline__ void ldsm4(uint32_t* r, uint32_t addr) {
    asm volatile("ldmatrix.sync.aligned.m8n8.x4.shared.b16 {%0,%1,%2,%3}, [%4];"
                 : "=r"(r[0]), "=r"(r[1]), "=r"(r[2]), "=r"(r[3]) : "r"(addr));
}
__device__ __forceinline__ void mma16816h(float* c, const uint32_t* a, const uint32_t* b) {
    asm volatile(
        "mma.sync.aligned.m16n8k16.row.col.f32.f16.f16.f32 "
        "{%0,%1,%2,%3}, {%4,%5,%6,%7}, {%8,%9}, {%0,%1,%2,%3};"
        : "+f"(c[0]), "+f"(c[1]), "+f"(c[2]), "+f"(c[3])
        : "r"(a[0]), "r"(a[1]), "r"(a[2]), "r"(a[3]), "r"(b[0]), "r"(b[1]));
}
__device__ __forceinline__ uint32_t packh(float lo, float hi) {
    __half2 h = __floats2half2_rn(lo, hi);
    return *(uint32_t*)&h;
}
#define CP_ASYNC16(sm_u32, gptr) \
    asm volatile("cp.async.cg.shared.global [%0], [%1], 16;" :: "r"(sm_u32), "l"(gptr))
#define CP_COMMIT() asm volatile("cp.async.commit_group;" ::: "memory")
#define CP_WAIT1()  asm volatile("cp.async.wait_group 1;" ::: "memory")
#define CP_WAIT0()  asm volatile("cp.async.wait_group 0;" ::: "memory")

// ---------------------------------------------------------------------------
// Convert kernels
// ---------------------------------------------------------------------------
__global__ void cvt_k(const float* __restrict__ in,
                      __half* __restrict__ out, int n)
{
    int i = blockIdx.x * blockDim.x + threadIdx.x;
    if (i >= n) return;
    out[i] = __float2half_rn(in[i]);
}

// Transpose + round: in [K][N] fp32 -> outT [N][K] fp16
__global__ __launch_bounds__(256) void tsplit_k(const float* __restrict__ in,
                                                __half* __restrict__ outT,
                                                int K, int N)
{
    __shared__ float tile[32][33];
    const int tx = threadIdx.x & 31;
    const int ty = threadIdx.x >> 5;       // 0..7
    const int n0 = blockIdx.x * 32;
    const int k0 = blockIdx.y * 32;
#pragma unroll
    for (int i = 0; i < 4; i++) {
        int kk = ty + 8 * i;
        tile[kk][tx] = in[(size_t)(k0 + kk) * N + n0 + tx];
    }
    __syncthreads();
#pragma unroll
    for (int i = 0; i < 4; i++) {
        int nn = ty + 8 * i;
        outT[(size_t)(n0 + nn) * K + k0 + tx] = __float2half_rn(tile[tx][nn]);
    }
}

// ---------------------------------------------------------------------------
// HMMA fp16 single-term GEMM: C[M,N] = A[M,K] * B^T  (A, B fp16; B [N][K])
// 128x128 block, 8 warps (warp tile 64x32), KC=32, 3-stage cp.async pipeline.
// ---------------------------------------------------------------------------
#define KC 32
#define NKC (GK / KC)            // 32
#define ROWB 80                  // 32 fp16 = 64B data + 16B pad
#define TILE_SB (128 * ROWB)     // 10240
#define STAGE_SB (2 * TILE_SB)   // A, B = 20480
#define NSTG 3
#define GEMM_SMEM_SZ (NSTG * STAGE_SB)  // 61440

__global__ __launch_bounds__(256) void gemm_hmma_k(
    const __half* __restrict__ ah,
    const __half* __restrict__ bT,
    float* __restrict__ C, int N)
{
    extern __shared__ char sm[];
    const uint32_t sb = smem_to_u32(sm);
    const int t = threadIdx.x;
    const int lane = t & 31;
    const int wid = t >> 5;
    const int wm = wid & 1;
    const int wn = wid >> 1;
    const size_t arow0 = (size_t)blockIdx.y * 128;
    const size_t brow0 = (size_t)blockIdx.x * 128;

    const __half* gsrc[2] = { ah + arow0 * GK, bT + brow0 * GK };

    auto issue_stage = [&](int c) {
        const uint32_t st = sb + (uint32_t)(c % NSTG) * STAGE_SB;
        const size_t k0 = (size_t)c * KC;
#pragma unroll
        for (int comp = 0; comp < 2; comp++) {
#pragma unroll
            for (int i = 0; i < 2; i++) {
                int u = t + i * 256;
                int r = u >> 2, ch = u & 3;
                const void* g = gsrc[comp] + (size_t)r * GK + k0 + ch * 8;
                CP_ASYNC16(st + comp * TILE_SB + r * ROWB + ch * 16, g);
            }
        }
    };

    float acc[4][4][4];
#pragma unroll
    for (int mt = 0; mt < 4; mt++)
#pragma unroll
        for (int nt = 0; nt < 4; nt++)
#pragma unroll
            for (int i = 0; i < 4; i++) acc[mt][nt][i] = 0.f;

    issue_stage(0); CP_COMMIT();
    issue_stage(1); CP_COMMIT();
    CP_WAIT1();
    __syncthreads();

    const int idx = lane & 7;
    const int sel = lane >> 3;

    for (int c = 0; c < NKC; c++) {
        if (c + 2 < NKC) issue_stage(c + 2);
        CP_COMMIT();
        const uint32_t st = sb + (uint32_t)(c % NSTG) * STAGE_SB;

#pragma unroll
        for (int j = 0; j < 2; j++) {
            uint32_t af[4][4], bf[4][2];
            const uint32_t acol = (uint32_t)((2 * j + (sel >> 1)) << 4);
#pragma unroll
            for (int mt = 0; mt < 4; mt++) {
                uint32_t ra = (uint32_t)(wm * 64 + mt * 16 + ((sel & 1) << 3) + idx);
                ldsm4(af[mt], st + ra * ROWB + acol);
            }
            {
                const uint32_t bcol = (uint32_t)((2 * j + (sel & 1)) << 4);
                uint32_t rb = (uint32_t)(wn * 32 + ((sel >> 1) << 3) + idx);
                uint32_t bd = st + TILE_SB + rb * ROWB + bcol;
                uint32_t tmp[4];
                ldsm4(tmp, bd);
                bf[0][0] = tmp[0]; bf[0][1] = tmp[1];
                bf[1][0] = tmp[2]; bf[1][1] = tmp[3];
                ldsm4(tmp, bd + 16 * ROWB);
                bf[2][0] = tmp[0]; bf[2][1] = tmp[1];
                bf[3][0] = tmp[2]; bf[3][1] = tmp[3];
            }
#pragma unroll
            for (int mt = 0; mt < 4; mt++)
#pragma unroll
                for (int nt = 0; nt < 4; nt++)
                    mma16816h(acc[mt][nt], af[mt], bf[nt]);
        }
        CP_WAIT1();
        __syncthreads();
    }

    const int g = lane >> 2, tg = lane & 3;
#pragma unroll
    for (int mt = 0; mt < 4; mt++) {
        size_t row0 = arow0 + wm * 64 + mt * 16 + g;
#pragma unroll
        for (int nt = 0; nt < 4; nt++) {
            size_t col = brow0 + wn * 32 + nt * 8 + tg * 2;
            *(float2*)(C + row0 * N + col) = make_float2(acc[mt][nt][0], acc[mt][nt][1]);
            *(float2*)(C + (row0 + 8) * N + col) = make_float2(acc[mt][nt][2], acc[mt][nt][3]);
        }
    }
}

// ---------------------------------------------------------------------------
// RoPE + round: reads g_qkv, rotates q (scaled) and k, writes fp16 in flash
// layout [bh][S][64].
// ---------------------------------------------------------------------------
__global__ void ropesplit_k(const int* __restrict__ pos)
{
    int idx = blockIdx.x * blockDim.x + threadIdx.x;
    const int total = ROWS * HH * 2 * 32;
    if (idx >= total) return;
    int i = idx & 31;
    int rest = idx >> 5;
    int comp = rest & 1; rest >>= 1;   // 0 = q, 1 = k
    int h = rest & 15;
    int row = rest >> 4;
    int b = row >> 11;                 // / SS
    int s = row & (SS - 1);
    int bh = b * HH + h;

    float p = (float)pos[row];
    float inv = powf(10000.0f, -(float)i * (1.0f / 32.0f));
    float sn, cs;
    sincosf(p * inv, &sn, &cs);

    const float* base = g_qkv + (size_t)row * (3 * DD) + h * TRIPLE + comp * HD;
    float x1 = base[i];
    float x2 = base[i + 32];
    float o1 = x1 * cs - x2 * sn;
    float o2 = x1 * sn + x2 * cs;
    if (comp == 0) { o1 *= 0.125f; o2 *= 0.125f; }

    __half* dh = (comp ? g_kh : g_qh) + ((size_t)bh * SS + s) * HD;
    dh[i] = __float2half_rn(o1);
    dh[i + 32] = __float2half_rn(o2);
}

// ---------------------------------------------------------------------------
// V transpose + round: g_qkv v-part -> g_vt [bh][64][S] fp16
// ---------------------------------------------------------------------------
__global__ __launch_bounds__(256) void vsplit_k()
{
    __shared__ float tile[64][65];
    const int bh = blockIdx.x;
    const int b = bh >> 4, h = bh & 15;
    const int s0 = blockIdx.y * 64;
    const int t = threadIdx.x;
#pragma unroll
    for (int i = 0; i < 16; i++) {
        int u = t + i * 256;
        int sl = u >> 6, d = u & 63;
        tile[sl][d] = g_qkv[(size_t)(b * SS + s0 + sl) * (3 * DD) + h * TRIPLE + 2 * HD + d];
    }
    __syncthreads();
#pragma unroll
    for (int i = 0; i < 16; i++) {
        int u = t + i * 256;
        int dl = u >> 6, sl = u & 63;
        g_vt[((size_t)bh * HD + dl) * SS + s0 + sl] = __float2half_rn(tile[sl][dl]);
    }
}

// ---------------------------------------------------------------------------
// HMMA causal flash attention — fp16 single-term.
// grid (S/128, BH), 256 threads (8 warps, warp = m16 q-tile).
// Q [128][64] fp16 resident in smem; K/V 64-key fp16 tiles double-buffered.
// ---------------------------------------------------------------------------
#define FQ 128
#define FKT 64
#define FSQ 0
#define FSKV 16384
#define FBUF 16384
#define FLASH_SMEM 49152

__device__ __forceinline__ uint32_t fsw(int r, int c) {
    return (uint32_t)((r << 7) + (((c ^ (r & 7))) << 4));
}

__global__ __launch_bounds__(256) void flashmma_k()
{
    extern __shared__ char sm[];
    const uint32_t sb = smem_to_u32(sm);
    const int t = threadIdx.x, lane = t & 31, w = t >> 5;
    const int idx = lane & 7, sel = lane >> 3;
    const int bh = blockIdx.y, b = bh >> 4, h = bh & 15;
    const int qt = (int)gridDim.x - 1 - (int)blockIdx.x;   // heavy tiles first
    const int q0 = qt * FQ;
    const int qw = q0 + w * 16;
    const int ntiles = q0 / FKT + 2;

    // Q tile cp.async
    {
        const __half* s0 = g_qh + ((size_t)bh * SS + q0) * HD;
#pragma unroll
        for (int i = 0; i < 4; i++) {
            int u = t + i * 256; int r = u >> 3, c = u & 7;
            CP_ASYNC16(sb + FSQ + fsw(r, c), s0 + (size_t)r * HD + c * 8);
        }
        CP_COMMIT();
    }

    auto ld_kv = [&](int ct) {
        const int k0 = ct * FKT;
        const uint32_t bd = sb + FSKV + (ct & 1) * FBUF;
        const __half* sk = g_kh + ((size_t)bh * SS + k0) * HD;
#pragma unroll
        for (int i = 0; i < 2; i++) {
            int u = t + i * 256; int r = u >> 3, c = u & 7;
            CP_ASYNC16(bd + fsw(r, c), sk + (size_t)r * HD + c * 8);
        }
        const __half* sv = g_vt + (size_t)bh * HD * SS + k0;
#pragma unroll
        for (int i = 0; i < 2; i++) {
            int u = t + i * 256; int r = u >> 3, c = u & 7;
            CP_ASYNC16(bd + 8192 + fsw(r, c), sv + (size_t)r * SS + c * 8);
        }
        CP_COMMIT();
    };

    ld_kv(0);
    CP_WAIT0();
    __syncthreads();

    // Q fragments (resident): 4 k16 chunks
    uint32_t qf[4][4];
#pragma unroll
    for (int j = 0; j < 4; j++) {
        int row = w * 16 + ((sel & 1) << 3) + idx;
        int ch = 2 * j + (sel >> 1);
        ldsm4(qf[j], sb + FSQ + fsw(row, ch));
    }

    float o[8][4];
#pragma unroll
    for (int nt = 0; nt < 8; nt++)
#pragma unroll
        for (int i = 0; i < 4; i++) o[nt][i] = 0.f;
    float m0 = -INFINITY, m1 = -INFINITY, l0 = 0.f, l1 = 0.f;
    const int r = lane >> 2, cb = (lane & 3) * 2;

    for (int c = 0; c < ntiles; c++) {
        if (c + 1 < ntiles) ld_kv(c + 1);
        const int k0 = c * FKT;
        const uint32_t kb = sb + FSKV + (c & 1) * FBUF;

        if (k0 <= qw + 15) {
            float s[8][4];
#pragma unroll
            for (int nt = 0; nt < 8; nt++)
#pragma unroll
                for (int i = 0; i < 4; i++) s[nt][i] = 0.f;

            // S = Q K^T
#pragma unroll
            for (int j = 0; j < 4; j++) {
                const int krow = ((sel >> 1) << 3) + idx;
                const int kch = 2 * j + (sel & 1);
#pragma unroll
                for (int np = 0; np < 4; np++) {
                    uint32_t th[4];
                    ldsm4(th, kb + fsw(np * 16 + krow, kch));
                    uint32_t b0[2] = { th[0], th[1] }, b1[2] = { th[2], th[3] };
                    mma16816h(s[2 * np],     qf[j], b0);
                    mma16816h(s[2 * np + 1], qf[j], b1);
                }
            }
            // causal mask
            if (k0 + FKT - 1 > qw) {
                const int row0 = qw + r, row1 = row0 + 8;
#pragma unroll
                for (int nt = 0; nt < 8; nt++) {
                    int c0 = k0 + nt * 8 + cb;
                    if (c0 > row0)     s[nt][0] = -INFINITY;
                    if (c0 + 1 > row0) s[nt][1] = -INFINITY;
                    if (c0 > row1)     s[nt][2] = -INFINITY;
                    if (c0 + 1 > row1) s[nt][3] = -INFINITY;
                }
            }
            // online softmax
            float mx0 = s[0][0], mx1 = s[0][2];
#pragma unroll
            for (int nt = 0; nt < 8; nt++) {
                mx0 = fmaxf(mx0, fmaxf(s[nt][0], s[nt][1]));
                mx1 = fmaxf(mx1, fmaxf(s[nt][2], s[nt][3]));
            }
            mx0 = fmaxf(mx0, __shfl_xor_sync(0xffffffffu, mx0, 1));
            mx0 = fmaxf(mx0, __shfl_xor_sync(0xffffffffu, mx0, 2));
            mx1 = fmaxf(mx1, __shfl_xor_sync(0xffffffffu, mx1, 1));
            mx1 = fmaxf(mx1, __shfl_xor_sync(0xffffffffu, mx1, 2));
            float mn0 = fmaxf(m0, mx0), mn1 = fmaxf(m1, mx1);
            float sc0 = __expf(m0 - mn0), sc1 = __expf(m1 - mn1);
            float rs0 = 0.f, rs1 = 0.f;
#pragma unroll
            for (int nt = 0; nt < 8; nt++) {
                s[nt][0] = __expf(s[nt][0] - mn0); rs0 += s[nt][0];
                s[nt][1] = __expf(s[nt][1] - mn0); rs0 += s[nt][1];
                s[nt][2] = __expf(s[nt][2] - mn1); rs1 += s[nt][2];
                s[nt][3] = __expf(s[nt][3] - mn1); rs1 += s[nt][3];
            }
            rs0 += __shfl_xor_sync(0xffffffffu, rs0, 1);
            rs0 += __shfl_xor_sync(0xffffffffu, rs0, 2);
            rs1 += __shfl_xor_sync(0xffffffffu, rs1, 1);
            rs1 += __shfl_xor_sync(0xffffffffu, rs1, 2);
            m0 = mn0; m1 = mn1;
            l0 = l0 * sc0 + rs0; l1 = l1 * sc1 + rs1;
#pragma unroll
            for (int nt = 0; nt < 8; nt++) {
                o[nt][0] *= sc0; o[nt][1] *= sc0;
                o[nt][2] *= sc1; o[nt][3] *= sc1;
            }
            // O += P V; P A-fragments from S fragments (single fp16)
#pragma unroll
            for (int j = 0; j < 4; j++) {
                uint32_t pa[4];
                pa[0] = packh(s[2 * j][0],     s[2 * j][1]);
                pa[1] = packh(s[2 * j][2],     s[2 * j][3]);
                pa[2] = packh(s[2 * j + 1][0], s[2 * j + 1][1]);
                pa[3] = packh(s[2 * j + 1][2], s[2 * j + 1][3]);
                const int vrow = ((sel >> 1) << 3) + idx;
                const int vch = 2 * j + (sel & 1);
#pragma unroll
                for (int np = 0; np < 4; np++) {
                    uint32_t th[4];
                    ldsm4(th, kb + 8192 + fsw(np * 16 + vrow, vch));
                    uint32_t b0[2] = { th[0], th[1] }, b1[2] = { th[2], th[3] };
                    mma16816h(o[2 * np],     pa, b0);
                    mma16816h(o[2 * np + 1], pa, b1);
                }
            }
        }
        __syncthreads();
        if (c + 1 < ntiles) { CP_WAIT0(); __syncthreads(); }
    }

    // epilogue: normalize, round to fp16, write g_ch [row][h*64+d]
    float i0 = 1.f / l0, i1 = 1.f / l1;
    const size_t row0 = (size_t)b * SS + qw + r;
    const size_t row1 = row0 + 8;
#pragma unroll
    for (int nt = 0; nt < 8; nt++) {
        int col = h * HD + nt * 8 + cb;
        *(uint32_t*)(g_ch + row0 * DD + col) = packh(o[nt][0] * i0, o[nt][1] * i0);
        *(uint32_t*)(g_ch + row1 * DD + col) = packh(o[nt][2] * i1, o[nt][3] * i1);
    }
}

// ---------------------------------------------------------------------------
// Launch
// Inputs: 0=inputs f32[B,S,D], 1=segment_positions i32[B,S], 2=mask (unused),
// 3=W_in f32[D,3D], 4=W_out f32[D,D]. Output: f32[B,S,D].
// ---------------------------------------------------------------------------
extern "C" void kernel_launch(void* const* d_in, const int* in_sizes, int n_in,
                              void* d_out, int out_size)
{
    const float* x    = (const float*)d_in[0];
    const int*   pos  = (const int*)d_in[1];
    const float* Win  = (const float*)d_in[3];
    const float* Wout = (const float*)d_in[4];
    float* out = (float*)d_out;

    float* qkv;
    __half *ah, *ch, *wT, *oT;
    cudaGetSymbolAddress((void**)&qkv, g_qkv);
    cudaGetSymbolAddress((void**)&ah, g_ah);
    cudaGetSymbolAddress((void**)&ch, g_ch);
    cudaGetSymbolAddress((void**)&wT, g_wT);
    cudaGetSymbolAddress((void**)&oT, g_oT);

    cudaFuncSetAttribute(gemm_hmma_k,
                         cudaFuncAttributeMaxDynamicSharedMemorySize, GEMM_SMEM_SZ);
    cudaFuncSetAttribute(flashmma_k,
                         cudaFuncAttributeMaxDynamicSharedMemorySize, FLASH_SMEM);

    // 0) round inputs to fp16; transpose+round weights to fp16
    {
        int n = ROWS * DD;
        cvt_k<<<(n + 255) / 256, 256>>>(x, ah, n);
    }
    tsplit_k<<<dim3(3 * DD / 32, DD / 32), 256>>>(Win, wT, DD, 3 * DD);
    tsplit_k<<<dim3(DD / 32, DD / 32), 256>>>(Wout, oT, DD, DD);

    // 1) QKV projection via fp16 HMMA
    gemm_hmma_k<<<dim3(3 * DD / 128, ROWS / 128), 256, GEMM_SMEM_SZ>>>(
        ah, wT, qkv, 3 * DD);

    // 2) RoPE + fp16 round into flash layouts; V transpose+round
    {
        int nrope = ROWS * HH * 2 * 32;
        ropesplit_k<<<(nrope + 255) / 256, 256>>>(pos);
    }
    vsplit_k<<<dim3(BB * HH, SS / 64), 256>>>();

    // 3) HMMA causal flash attention (fp16 single-term; writes fp16 g_ch)
    flashmma_k<<<dim3(SS / FQ, BB * HH), 256, FLASH_SMEM>>>();

    // 4) Output projection via fp16 HMMA
    gemm_hmma_k<<<dim3(DD / 128, ROWS / 128), 256, GEMM_SMEM_SZ>>>(
        ch, oT, out, DD);
}

// round 10
// speedup vs baseline: 7.5983x; 1.0512x over previous
#include <cuda_runtime.h>
#include <cuda_bf16.h>
#include <cuda_fp16.h>
#include <math.h>
#include <stdint.h>

#define BB 2
#define SS 2048
#define DD 1024
#define HH 16
#define HD 64
#define ROWS (BB*SS)      // 4096
#define TRIPLE (3*HD)     // 192 floats per (row, head)
#define GK 1024           // GEMM K dim (fixed)

// ---------------------------------------------------------------------------
// Scratch (static device globals; no allocation at runtime)
// ---------------------------------------------------------------------------
__device__ float g_qkv[(size_t)ROWS * 3 * DD];        // [ROWS][H][192] fp32
__device__ __half g_ah[(size_t)ROWS * DD];            // inputs fp16 [row][K]
__device__ __half g_ch[(size_t)ROWS * DD];            // attn out fp16 [row][D]
__device__ __half g_wT[(size_t)3 * DD * DD];          // W_in^T fp16 [3072][1024]
__device__ __half g_oT[(size_t)DD * DD];              // W_out^T fp16 [1024][1024]
// flash operands (fp16 single-term): Q,K [bh][S][64]; V^T [bh][64][S]
__device__ __half g_qh[(size_t)BB * HH * SS * HD];
__device__ __half g_kh[(size_t)BB * HH * SS * HD];
__device__ __half g_vt[(size_t)BB * HH * HD * SS];

// ---------------------------------------------------------------------------
// PTX helpers (portable: mma.sync / ldmatrix / cp.async — no arch-'a' features)
// ---------------------------------------------------------------------------
__device__ __forceinline__ uint32_t smem_to_u32(const void* smem_ptr) {
    uint32_t addr;
    asm("{ .reg .u64 tmp; cvta.to.shared.u64 tmp, %1; cvt.u32.u64 %0, tmp; }"
        : "=r"(addr) : "l"(smem_ptr));
    return addr;
}
__device__ __forceinline__ void ldsm4(uint32_t* r, uint32_t addr) {
    asm volatile("ldmatrix.sync.aligned.m8n8.x4.shared.b16 {%0,%1,%2,%3}, [%4];"
                 : "=r"(r[0]), "=r"(r[1]), "=r"(r[2]), "=r"(r[3]) : "r"(addr));
}
__device__ __forceinline__ void mma16816h(float* c, const uint32_t* a, const uint32_t* b) {
    asm volatile(
        "mma.sync.aligned.m16n8k16.row.col.f32.f16.f16.f32 "
        "{%0,%1,%2,%3}, {%4,%5,%6,%7}, {%8,%9}, {%0,%1,%2,%3};"
        : "+f"(c[0]), "+f"(c[1]), "+f"(c[2]), "+f"(c[3])
        : "r"(a[0]), "r"(a[1]), "r"(a[2]), "r"(a[3]), "r"(b[0]), "r"(b[1]));
}
__device__ __forceinline__ uint32_t packh(float lo, float hi) {
    __half2 h = __floats2half2_rn(lo, hi);
    return *(uint32_t*)&h;
}
#define CP_ASYNC16(sm_u32, gptr) \
    asm volatile("cp.async.cg.shared.global [%0], [%1], 16;" :: "r"(sm_u32), "l"(gptr))
#define CP_COMMIT() asm volatile("cp.async.commit_group;" ::: "memory")
#define CP_WAIT1()  asm volatile("cp.async.wait_group 1;" ::: "memory")
#define CP_WAIT0()  asm volatile("cp.async.wait_group 0;" ::: "memory")

// ---------------------------------------------------------------------------
// Convert kernels
// ---------------------------------------------------------------------------
__global__ void cvt_k(const float* __restrict__ in,
                      __half* __restrict__ out, int n4)
{
    int i = blockIdx.x * blockDim.x + threadIdx.x;
    if (i >= n4) return;
    float4 v = *(const float4*)(in + 4 * (size_t)i);
    uint32_t lo = packh(v.x, v.y), hi = packh(v.z, v.w);
    *(uint2*)(out + 4 * (size_t)i) = make_uint2(lo, hi);
}

// Transpose + round: in [K][N] fp32 -> outT [N][K] fp16
__global__ __launch_bounds__(256) void tsplit_k(const float* __restrict__ in,
                                                __half* __restrict__ outT,
                                                int K, int N)
{
    __shared__ float tile[32][33];
    const int tx = threadIdx.x & 31;
    const int ty = threadIdx.x >> 5;       // 0..7
    const int n0 = blockIdx.x * 32;
    const int k0 = blockIdx.y * 32;
#pragma unroll
    for (int i = 0; i < 4; i++) {
        int kk = ty + 8 * i;
        tile[kk][tx] = in[(size_t)(k0 + kk) * N + n0 + tx];
    }
    __syncthreads();
#pragma unroll
    for (int i = 0; i < 4; i++) {
        int nn = ty + 8 * i;
        outT[(size_t)(n0 + nn) * K + k0 + tx] = __float2half_rn(tile[tx][nn]);
    }
}

// ---------------------------------------------------------------------------
// HMMA fp16 GEMM: C[M,N] = A[M,K] * B^T  (A, B fp16; B [N][K])
// CTA 128x256, 8 warps (warp tile 64x64), KC=32, 3-stage cp.async pipeline.
// ---------------------------------------------------------------------------
#define KC 32
#define NKC (GK / KC)            // 32
#define ROWB 80                  // 32 fp16 = 64B data + 16B pad
#define A_SB (128 * ROWB)        // 10240
#define B_SB (256 * ROWB)        // 20480
#define STAGE_SB (A_SB + B_SB)   // 30720
#define NSTG 3
#define GEMM_SMEM_SZ (NSTG * STAGE_SB)  // 92160

__global__ __launch_bounds__(256, 1) void gemm_hmma_k(
    const __half* __restrict__ ah,
    const __half* __restrict__ bT,
    float* __restrict__ C, int N)
{
    extern __shared__ char sm[];
    const uint32_t sb = smem_to_u32(sm);
    const int t = threadIdx.x;
    const int lane = t & 31;
    const int wid = t >> 5;
    const int wm = wid & 1;          // 2 m-blocks of 64
    const int wn = wid >> 1;         // 4 n-blocks of 64
    const size_t arow0 = (size_t)blockIdx.y * 128;
    const size_t brow0 = (size_t)blockIdx.x * 256;

    const __half* ag = ah + arow0 * GK;
    const __half* bg = bT + brow0 * GK;

    auto issue_stage = [&](int c) {
        const uint32_t st = sb + (uint32_t)(c % NSTG) * STAGE_SB;
        const size_t k0 = (size_t)c * KC;
        // A: 128 rows x 64B = 512 16B chunks (2/thread)
#pragma unroll
        for (int i = 0; i < 2; i++) {
            int u = t + i * 256;
            int r = u >> 2, ch = u & 3;
            CP_ASYNC16(st + r * ROWB + ch * 16, ag + (size_t)r * GK + k0 + ch * 8);
        }
        // B: 256 rows x 64B = 1024 16B chunks (4/thread)
#pragma unroll
        for (int i = 0; i < 4; i++) {
            int u = t + i * 256;
            int r = u >> 2, ch = u & 3;
            CP_ASYNC16(st + A_SB + r * ROWB + ch * 16, bg + (size_t)r * GK + k0 + ch * 8);
        }
    };

    float acc[4][8][4];
#pragma unroll
    for (int mt = 0; mt < 4; mt++)
#pragma unroll
        for (int nt = 0; nt < 8; nt++)
#pragma unroll
            for (int i = 0; i < 4; i++) acc[mt][nt][i] = 0.f;

    issue_stage(0); CP_COMMIT();
    issue_stage(1); CP_COMMIT();
    CP_WAIT1();
    __syncthreads();

    const int idx = lane & 7;
    const int sel = lane >> 3;

    for (int c = 0; c < NKC; c++) {
        if (c + 2 < NKC) issue_stage(c + 2);
        CP_COMMIT();
        const uint32_t st = sb + (uint32_t)(c % NSTG) * STAGE_SB;

#pragma unroll
        for (int j = 0; j < 2; j++) {
            uint32_t af[4][4], bf[8][2];
            const uint32_t acol = (uint32_t)((2 * j + (sel >> 1)) << 4);
#pragma unroll
            for (int mt = 0; mt < 4; mt++) {
                uint32_t ra = (uint32_t)(wm * 64 + mt * 16 + ((sel & 1) << 3) + idx);
                ldsm4(af[mt], st + ra * ROWB + acol);
            }
            {
                const uint32_t bcol = (uint32_t)((2 * j + (sel & 1)) << 4);
                uint32_t rb = (uint32_t)(wn * 64 + ((sel >> 1) << 3) + idx);
                uint32_t bd = st + A_SB + rb * ROWB + bcol;
                uint32_t tmp[4];
#pragma unroll
                for (int nb = 0; nb < 4; nb++) {
                    ldsm4(tmp, bd + nb * 16 * ROWB);
                    bf[2 * nb][0]     = tmp[0]; bf[2 * nb][1]     = tmp[1];
                    bf[2 * nb + 1][0] = tmp[2]; bf[2 * nb + 1][1] = tmp[3];
                }
            }
#pragma unroll
            for (int mt = 0; mt < 4; mt++)
#pragma unroll
                for (int nt = 0; nt < 8; nt++)
                    mma16816h(acc[mt][nt], af[mt], bf[nt]);
        }
        CP_WAIT1();
        __syncthreads();
    }

    const int g = lane >> 2, tg = lane & 3;
#pragma unroll
    for (int mt = 0; mt < 4; mt++) {
        size_t row0 = arow0 + wm * 64 + mt * 16 + g;
#pragma unroll
        for (int nt = 0; nt < 8; nt++) {
            size_t col = brow0 + wn * 64 + nt * 8 + tg * 2;
            *(float2*)(C + row0 * N + col) = make_float2(acc[mt][nt][0], acc[mt][nt][1]);
            *(float2*)(C + (row0 + 8) * N + col) = make_float2(acc[mt][nt][2], acc[mt][nt][3]);
        }
    }
}

// ---------------------------------------------------------------------------
// RoPE + round: reads g_qkv, rotates q (scaled) and k, writes fp16 in flash
// layout [bh][S][64]. Thread handles 2 adjacent i (u32 stores).
// ---------------------------------------------------------------------------
__global__ void ropesplit_k(const int* __restrict__ pos)
{
    int idx = blockIdx.x * blockDim.x + threadIdx.x;
    const int total = ROWS * HH * 2 * 16;
    if (idx >= total) return;
    int i2 = (idx & 15) * 2;           // 0,2,..,30
    int rest = idx >> 4;
    int comp = rest & 1; rest >>= 1;   // 0 = q, 1 = k
    int h = rest & 15;
    int row = rest >> 4;
    int b = row >> 11;                 // / SS
    int s = row & (SS - 1);
    int bh = b * HH + h;

    float p = (float)pos[row];
    const float* base = g_qkv + (size_t)row * (3 * DD) + h * TRIPLE + comp * HD;
    float2 x1 = *(const float2*)(base + i2);
    float2 x2 = *(const float2*)(base + i2 + 32);

    float o1a, o2a, o1b, o2b;
    {
        float inv = powf(10000.0f, -(float)i2 * (1.0f / 32.0f));
        float sn, cs; sincosf(p * inv, &sn, &cs);
        o1a = x1.x * cs - x2.x * sn;
        o2a = x1.x * sn + x2.x * cs;
    }
    {
        float inv = powf(10000.0f, -(float)(i2 + 1) * (1.0f / 32.0f));
        float sn, cs; sincosf(p * inv, &sn, &cs);
        o1b = x1.y * cs - x2.y * sn;
        o2b = x1.y * sn + x2.y * cs;
    }
    if (comp == 0) { o1a *= 0.125f; o2a *= 0.125f; o1b *= 0.125f; o2b *= 0.125f; }

    __half* dh = (comp ? g_kh : g_qh) + ((size_t)bh * SS + s) * HD;
    *(uint32_t*)(dh + i2)      = packh(o1a, o1b);
    *(uint32_t*)(dh + i2 + 32) = packh(o2a, o2b);
}

// ---------------------------------------------------------------------------
// V transpose + round: g_qkv v-part -> g_vt [bh][64][S] fp16
// ---------------------------------------------------------------------------
__global__ __launch_bounds__(256) void vsplit_k()
{
    __shared__ float tile[64][65];
    const int bh = blockIdx.x;
    const int b = bh >> 4, h = bh & 15;
    const int s0 = blockIdx.y * 64;
    const int t = threadIdx.x;
#pragma unroll
    for (int i = 0; i < 16; i++) {
        int u = t + i * 256;
        int sl = u >> 6, d = u & 63;
        tile[sl][d] = g_qkv[(size_t)(b * SS + s0 + sl) * (3 * DD) + h * TRIPLE + 2 * HD + d];
    }
    __syncthreads();
#pragma unroll
    for (int i = 0; i < 8; i++) {
        int u = t + i * 256;
        int dl = u >> 5, sl2 = (u & 31) * 2;
        uint32_t v = packh(tile[sl2][dl], tile[sl2 + 1][dl]);
        *(uint32_t*)(g_vt + ((size_t)bh * HD + dl) * SS + s0 + sl2) = v;
    }
}

// ---------------------------------------------------------------------------
// HMMA causal flash attention — fp16 single-term.
// grid (S/128, BH), 256 threads (8 warps, warp = m16 q-tile).
// ---------------------------------------------------------------------------
#define FQ 128
#define FKT 64
#define FSQ 0
#define FSKV 16384
#define FBUF 16384
#define FLASH_SMEM 49152

__device__ __forceinline__ uint32_t fsw(int r, int c) {
    return (uint32_t)((r << 7) + (((c ^ (r & 7))) << 4));
}

__global__ __launch_bounds__(256) void flashmma_k()
{
    extern __shared__ char sm[];
    const uint32_t sb = smem_to_u32(sm);
    const int t = threadIdx.x, lane = t & 31, w = t >> 5;
    const int idx = lane & 7, sel = lane >> 3;
    const int bh = blockIdx.y, b = bh >> 4, h = bh & 15;
    const int qt = (int)gridDim.x - 1 - (int)blockIdx.x;   // heavy tiles first
    const int q0 = qt * FQ;
    const int qw = q0 + w * 16;
    const int ntiles = q0 / FKT + 2;

    // Q tile cp.async
    {
        const __half* s0 = g_qh + ((size_t)bh * SS + q0) * HD;
#pragma unroll
        for (int i = 0; i < 4; i++) {
            int u = t + i * 256; int r = u >> 3, c = u & 7;
            CP_ASYNC16(sb + FSQ + fsw(r, c), s0 + (size_t)r * HD + c * 8);
        }
        CP_COMMIT();
    }

    auto ld_kv = [&](int ct) {
        const int k0 = ct * FKT;
        const uint32_t bd = sb + FSKV + (ct & 1) * FBUF;
        const __half* sk = g_kh + ((size_t)bh * SS + k0) * HD;
#pragma unroll
        for (int i = 0; i < 2; i++) {
            int u = t + i * 256; int r = u >> 3, c = u & 7;
            CP_ASYNC16(bd + fsw(r, c), sk + (size_t)r * HD + c * 8);
        }
        const __half* sv = g_vt + (size_t)bh * HD * SS + k0;
#pragma unroll
        for (int i = 0; i < 2; i++) {
            int u = t + i * 256; int r = u >> 3, c = u & 7;
            CP_ASYNC16(bd + 8192 + fsw(r, c), sv + (size_t)r * SS + c * 8);
        }
        CP_COMMIT();
    };

    ld_kv(0);
    CP_WAIT0();
    __syncthreads();

    // Q fragments (resident): 4 k16 chunks
    uint32_t qf[4][4];
#pragma unroll
    for (int j = 0; j < 4; j++) {
        int row = w * 16 + ((sel & 1) << 3) + idx;
        int ch = 2 * j + (sel >> 1);
        ldsm4(qf[j], sb + FSQ + fsw(row, ch));
    }

    float o[8][4];
#pragma unroll
    for (int nt = 0; nt < 8; nt++)
#pragma unroll
        for (int i = 0; i < 4; i++) o[nt][i] = 0.f;
    float m0 = -INFINITY, m1 = -INFINITY, l0 = 0.f, l1 = 0.f;
    const int r = lane >> 2, cb = (lane & 3) * 2;

    for (int c = 0; c < ntiles; c++) {
        if (c + 1 < ntiles) ld_kv(c + 1);
        const int k0 = c * FKT;
        const uint32_t kb = sb + FSKV + (c & 1) * FBUF;

        if (k0 <= qw + 15) {
            float s[8][4];
#pragma unroll
            for (int nt = 0; nt < 8; nt++)
#pragma unroll
                for (int i = 0; i < 4; i++) s[nt][i] = 0.f;

            // S = Q K^T
#pragma unroll
            for (int j = 0; j < 4; j++) {
                const int krow = ((sel >> 1) << 3) + idx;
                const int kch = 2 * j + (sel & 1);
#pragma unroll
                for (int np = 0; np < 4; np++) {
                    uint32_t th[4];
                    ldsm4(th, kb + fsw(np * 16 + krow, kch));
                    uint32_t b0[2] = { th[0], th[1] }, b1[2] = { th[2], th[3] };
                    mma16816h(s[2 * np],     qf[j], b0);
                    mma16816h(s[2 * np + 1], qf[j], b1);
                }
            }
            // causal mask
            if (k0 + FKT - 1 > qw) {
                const int row0 = qw + r, row1 = row0 + 8;
#pragma unroll
                for (int nt = 0; nt < 8; nt++) {
                    int c0 = k0 + nt * 8 + cb;
                    if (c0 > row0)     s[nt][0] = -INFINITY;
                    if (c0 + 1 > row0) s[nt][1] = -INFINITY;
                    if (c0 > row1)     s[nt][2] = -INFINITY;
                    if (c0 + 1 > row1) s[nt][3] = -INFINITY;
                }
            }
            // online softmax
            float mx0 = s[0][0], mx1 = s[0][2];
#pragma unroll
            for (int nt = 0; nt < 8; nt++) {
                mx0 = fmaxf(mx0, fmaxf(s[nt][0], s[nt][1]));
                mx1 = fmaxf(mx1, fmaxf(s[nt][2], s[nt][3]));
            }
            mx0 = fmaxf(mx0, __shfl_xor_sync(0xffffffffu, mx0, 1));
            mx0 = fmaxf(mx0, __shfl_xor_sync(0xffffffffu, mx0, 2));
            mx1 = fmaxf(mx1, __shfl_xor_sync(0xffffffffu, mx1, 1));
            mx1 = fmaxf(mx1, __shfl_xor_sync(0xffffffffu, mx1, 2));
            float mn0 = fmaxf(m0, mx0), mn1 = fmaxf(m1, mx1);
            float sc0 = __expf(m0 - mn0), sc1 = __expf(m1 - mn1);
            float rs0 = 0.f, rs1 = 0.f;
#pragma unroll
            for (int nt = 0; nt < 8; nt++) {
                s[nt][0] = __expf(s[nt][0] - mn0); rs0 += s[nt][0];
                s[nt][1] = __expf(s[nt][1] - mn0); rs0 += s[nt][1];
                s[nt][2] = __expf(s[nt][2] - mn1); rs1 += s[nt][2];
                s[nt][3] = __expf(s[nt][3] - mn1); rs1 += s[nt][3];
            }
            rs0 += __shfl_xor_sync(0xffffffffu, rs0, 1);
            rs0 += __shfl_xor_sync(0xffffffffu, rs0, 2);
            rs1 += __shfl_xor_sync(0xffffffffu, rs1, 1);
            rs1 += __shfl_xor_sync(0xffffffffu, rs1, 2);
            m0 = mn0; m1 = mn1;
            l0 = l0 * sc0 + rs0; l1 = l1 * sc1 + rs1;
#pragma unroll
            for (int nt = 0; nt < 8; nt++) {
                o[nt][0] *= sc0; o[nt][1] *= sc0;
                o[nt][2] *= sc1; o[nt][3] *= sc1;
            }
            // O += P V (single fp16 P)
#pragma unroll
            for (int j = 0; j < 4; j++) {
                uint32_t pa[4];
                pa[0] = packh(s[2 * j][0],     s[2 * j][1]);
                pa[1] = packh(s[2 * j][2],     s[2 * j][3]);
                pa[2] = packh(s[2 * j + 1][0], s[2 * j + 1][1]);
                pa[3] = packh(s[2 * j + 1][2], s[2 * j + 1][3]);
                const int vrow = ((sel >> 1) << 3) + idx;
                const int vch = 2 * j + (sel & 1);
#pragma unroll
                for (int np = 0; np < 4; np++) {
                    uint32_t th[4];
                    ldsm4(th, kb + 8192 + fsw(np * 16 + vrow, vch));
                    uint32_t b0[2] = { th[0], th[1] }, b1[2] = { th[2], th[3] };
                    mma16816h(o[2 * np],     pa, b0);
                    mma16816h(o[2 * np + 1], pa, b1);
                }
            }
        }
        __syncthreads();
        if (c + 1 < ntiles) { CP_WAIT0(); __syncthreads(); }
    }

    // epilogue: normalize, round to fp16, write g_ch [row][h*64+d]
    float i0 = 1.f / l0, i1 = 1.f / l1;
    const size_t row0 = (size_t)b * SS + qw + r;
    const size_t row1 = row0 + 8;
#pragma unroll
    for (int nt = 0; nt < 8; nt++) {
        int col = h * HD + nt * 8 + cb;
        *(uint32_t*)(g_ch + row0 * DD + col) = packh(o[nt][0] * i0, o[nt][1] * i0);
        *(uint32_t*)(g_ch + row1 * DD + col) = packh(o[nt][2] * i1, o[nt][3] * i1);
    }
}

// ---------------------------------------------------------------------------
// Launch
// Inputs: 0=inputs f32[B,S,D], 1=segment_positions i32[B,S], 2=mask (unused),
// 3=W_in f32[D,3D], 4=W_out f32[D,D]. Output: f32[B,S,D].
// ---------------------------------------------------------------------------
extern "C" void kernel_launch(void* const* d_in, const int* in_sizes, int n_in,
                              void* d_out, int out_size)
{
    const float* x    = (const float*)d_in[0];
    const int*   pos  = (const int*)d_in[1];
    const float* Win  = (const float*)d_in[3];
    const float* Wout = (const float*)d_in[4];
    float* out = (float*)d_out;

    float* qkv;
    __half *ah, *ch, *wT, *oT;
    cudaGetSymbolAddress((void**)&qkv, g_qkv);
    cudaGetSymbolAddress((void**)&ah, g_ah);
    cudaGetSymbolAddress((void**)&ch, g_ch);
    cudaGetSymbolAddress((void**)&wT, g_wT);
    cudaGetSymbolAddress((void**)&oT, g_oT);

    cudaFuncSetAttribute(gemm_hmma_k,
                         cudaFuncAttributeMaxDynamicSharedMemorySize, GEMM_SMEM_SZ);
    cudaFuncSetAttribute(flashmma_k,
                         cudaFuncAttributeMaxDynamicSharedMemorySize, FLASH_SMEM);

    // 0) round inputs to fp16; transpose+round weights to fp16
    {
        int n4 = ROWS * DD / 4;
        cvt_k<<<(n4 + 255) / 256, 256>>>(x, ah, n4);
    }
    tsplit_k<<<dim3(3 * DD / 32, DD / 32), 256>>>(Win, wT, DD, 3 * DD);
    tsplit_k<<<dim3(DD / 32, DD / 32), 256>>>(Wout, oT, DD, DD);

    // 1) QKV projection via fp16 HMMA (CTA 128x256)
    gemm_hmma_k<<<dim3(3 * DD / 256, ROWS / 128), 256, GEMM_SMEM_SZ>>>(
        ah, wT, qkv, 3 * DD);

    // 2) RoPE + fp16 round into flash layouts; V transpose+round
    {
        int nrope = ROWS * HH * 2 * 16;
        ropesplit_k<<<(nrope + 255) / 256, 256>>>(pos);
    }
    vsplit_k<<<dim3(BB * HH, SS / 64), 256>>>();

    // 3) HMMA causal flash attention (fp16 single-term; writes fp16 g_ch)
    flashmma_k<<<dim3(SS / FQ, BB * HH), 256, FLASH_SMEM>>>();

    // 4) Output projection via fp16 HMMA
    gemm_hmma_k<<<dim3(DD / 256, ROWS / 128), 256, GEMM_SMEM_SZ>>>(
        ch, oT, out, DD);
}

// round 11
// speedup vs baseline: 8.3487x; 1.0988x over previous
#include <cuda_runtime.h>
#include <cuda_bf16.h>
#include <cuda_fp16.h>
#include <math.h>
#include <stdint.h>

#define BB 2
#define SS 2048
#define DD 1024
#define HH 16
#define HD 64
#define ROWS (BB*SS)      // 4096
#define TRIPLE (3*HD)     // 192 floats per (row, head)
#define GK 1024           // GEMM K dim (fixed)

// ---------------------------------------------------------------------------
// Scratch (static device globals; no allocation at runtime)
// ---------------------------------------------------------------------------
__device__ float g_qkv[(size_t)ROWS * 3 * DD];        // [ROWS][H][192] fp32
__device__ __half g_ah[(size_t)ROWS * DD];            // inputs fp16 [row][K]
__device__ __half g_ch[(size_t)ROWS * DD];            // attn out fp16 [row][D]
__device__ __half g_wT[(size_t)3 * DD * DD];          // W_in^T fp16 [3072][1024]
__device__ __half g_oT[(size_t)DD * DD];              // W_out^T fp16 [1024][1024]
// flash operands (fp16 single-term): Q,K [bh][S][64]; V^T [bh][64][S]
__device__ __half g_qh[(size_t)BB * HH * SS * HD];
__device__ __half g_kh[(size_t)BB * HH * SS * HD];
__device__ __half g_vt[(size_t)BB * HH * HD * SS];

// ---------------------------------------------------------------------------
// PTX helpers (portable: mma.sync / ldmatrix / cp.async — no arch-'a' features)
// ---------------------------------------------------------------------------
__device__ __forceinline__ uint32_t smem_to_u32(const void* smem_ptr) {
    uint32_t addr;
    asm("{ .reg .u64 tmp; cvta.to.shared.u64 tmp, %1; cvt.u32.u64 %0, tmp; }"
        : "=r"(addr) : "l"(smem_ptr));
    return addr;
}
__device__ __forceinline__ void ldsm4(uint32_t* r, uint32_t addr) {
    asm volatile("ldmatrix.sync.aligned.m8n8.x4.shared.b16 {%0,%1,%2,%3}, [%4];"
                 : "=r"(r[0]), "=r"(r[1]), "=r"(r[2]), "=r"(r[3]) : "r"(addr));
}
__device__ __forceinline__ void mma16816h(float* c, const uint32_t* a, const uint32_t* b) {
    asm volatile(
        "mma.sync.aligned.m16n8k16.row.col.f32.f16.f16.f32 "
        "{%0,%1,%2,%3}, {%4,%5,%6,%7}, {%8,%9}, {%0,%1,%2,%3};"
        : "+f"(c[0]), "+f"(c[1]), "+f"(c[2]), "+f"(c[3])
        : "r"(a[0]), "r"(a[1]), "r"(a[2]), "r"(a[3]), "r"(b[0]), "r"(b[1]));
}
__device__ __forceinline__ uint32_t packh(float lo, float hi) {
    __half2 h = __floats2half2_rn(lo, hi);
    return *(uint32_t*)&h;
}
#define CP_ASYNC16(sm_u32, gptr) \
    asm volatile("cp.async.cg.shared.global [%0], [%1], 16;" :: "r"(sm_u32), "l"(gptr))
#define CP_COMMIT() asm volatile("cp.async.commit_group;" ::: "memory")
#define CP_WAIT1()  asm volatile("cp.async.wait_group 1;" ::: "memory")
#define CP_WAIT0()  asm volatile("cp.async.wait_group 0;" ::: "memory")

// ---------------------------------------------------------------------------
// Convert kernels
// ---------------------------------------------------------------------------
__global__ void cvt_k(const float* __restrict__ in,
                      __half* __restrict__ out, int n4)
{
    int i = blockIdx.x * blockDim.x + threadIdx.x;
    if (i >= n4) return;
    float4 v = *(const float4*)(in + 4 * (size_t)i);
    uint32_t lo = packh(v.x, v.y), hi = packh(v.z, v.w);
    *(uint2*)(out + 4 * (size_t)i) = make_uint2(lo, hi);
}

// Transpose + round: in [K][N] fp32 -> outT [N][K] fp16
__global__ __launch_bounds__(256) void tsplit_k(const float* __restrict__ in,
                                                __half* __restrict__ outT,
                                                int K, int N)
{
    __shared__ float tile[32][33];
    const int tx = threadIdx.x & 31;
    const int ty = threadIdx.x >> 5;       // 0..7
    const int n0 = blockIdx.x * 32;
    const int k0 = blockIdx.y * 32;
#pragma unroll
    for (int i = 0; i < 4; i++) {
        int kk = ty + 8 * i;
        tile[kk][tx] = in[(size_t)(k0 + kk) * N + n0 + tx];
    }
    __syncthreads();
#pragma unroll
    for (int i = 0; i < 4; i++) {
        int nn = ty + 8 * i;
        outT[(size_t)(n0 + nn) * K + k0 + tx] = __float2half_rn(tile[tx][nn]);
    }
}

// ---------------------------------------------------------------------------
// HMMA fp16 GEMM: C[M,N] = A[M,K] * B^T  (A, B fp16; B [N][K])
// CTA 128x128, 8 warps (warp tile 64x32), KC=64 (4 k16-steps/iter),
// 3-stage cp.async pipeline, one __syncthreads per iteration, 2 CTAs/SM.
// ---------------------------------------------------------------------------
#define KC 64
#define NKC (GK / KC)            // 16
#define ROWB 144                 // 64 fp16 = 128B data + 16B pad
#define TILE_SB (128 * ROWB)     // 18432
#define STAGE_SB (2 * TILE_SB)   // A, B = 36864
#define NSTG 3
#define GEMM_SMEM_SZ (NSTG * STAGE_SB)  // 110592

__global__ __launch_bounds__(256, 2) void gemm_hmma_k(
    const __half* __restrict__ ah,
    const __half* __restrict__ bT,
    float* __restrict__ C, int N)
{
    extern __shared__ char sm[];
    const uint32_t sb = smem_to_u32(sm);
    const int t = threadIdx.x;
    const int lane = t & 31;
    const int wid = t >> 5;
    const int wm = wid & 1;          // 2 m-blocks of 64
    const int wn = wid >> 1;         // 4 n-blocks of 32
    const size_t arow0 = (size_t)blockIdx.y * 128;
    const size_t brow0 = (size_t)blockIdx.x * 128;

    const __half* gsrc[2] = { ah + arow0 * GK, bT + brow0 * GK };

    auto issue_stage = [&](int c) {
        const uint32_t st = sb + (uint32_t)(c % NSTG) * STAGE_SB;
        const size_t k0 = (size_t)c * KC;
#pragma unroll
        for (int comp = 0; comp < 2; comp++) {
#pragma unroll
            for (int i = 0; i < 4; i++) {
                int u = t + i * 256;
                int r = u >> 3, ch = u & 7;
                const void* g = gsrc[comp] + (size_t)r * GK + k0 + ch * 8;
                CP_ASYNC16(st + comp * TILE_SB + r * ROWB + ch * 16, g);
            }
        }
    };

    float acc[4][4][4];
#pragma unroll
    for (int mt = 0; mt < 4; mt++)
#pragma unroll
        for (int nt = 0; nt < 4; nt++)
#pragma unroll
            for (int i = 0; i < 4; i++) acc[mt][nt][i] = 0.f;

    issue_stage(0); CP_COMMIT();
    issue_stage(1); CP_COMMIT();
    CP_WAIT1();
    __syncthreads();

    const int idx = lane & 7;
    const int sel = lane >> 3;

    for (int c = 0; c < NKC; c++) {
        if (c + 2 < NKC) issue_stage(c + 2);
        CP_COMMIT();
        const uint32_t st = sb + (uint32_t)(c % NSTG) * STAGE_SB;

#pragma unroll
        for (int j = 0; j < 4; j++) {           // four k16 steps per KC=64
            uint32_t af[4][4], bf[4][2];
            const uint32_t acol = (uint32_t)((2 * j + (sel >> 1)) << 4);
#pragma unroll
            for (int mt = 0; mt < 4; mt++) {
                uint32_t ra = (uint32_t)(wm * 64 + mt * 16 + ((sel & 1) << 3) + idx);
                ldsm4(af[mt], st + ra * ROWB + acol);
            }
            {
                const uint32_t bcol = (uint32_t)((2 * j + (sel & 1)) << 4);
                uint32_t rb = (uint32_t)(wn * 32 + ((sel >> 1) << 3) + idx);
                uint32_t bd = st + TILE_SB + rb * ROWB + bcol;
                uint32_t tmp[4];
                ldsm4(tmp, bd);
                bf[0][0] = tmp[0]; bf[0][1] = tmp[1];
                bf[1][0] = tmp[2]; bf[1][1] = tmp[3];
                ldsm4(tmp, bd + 16 * ROWB);
                bf[2][0] = tmp[0]; bf[2][1] = tmp[1];
                bf[3][0] = tmp[2]; bf[3][1] = tmp[3];
            }
#pragma unroll
            for (int mt = 0; mt < 4; mt++)
#pragma unroll
                for (int nt = 0; nt < 4; nt++)
                    mma16816h(acc[mt][nt], af[mt], bf[nt]);
        }
        CP_WAIT1();
        __syncthreads();
    }

    const int g = lane >> 2, tg = lane & 3;
#pragma unroll
    for (int mt = 0; mt < 4; mt++) {
        size_t row0 = arow0 + wm * 64 + mt * 16 + g;
#pragma unroll
        for (int nt = 0; nt < 4; nt++) {
            size_t col = brow0 + wn * 32 + nt * 8 + tg * 2;
            *(float2*)(C + row0 * N + col) = make_float2(acc[mt][nt][0], acc[mt][nt][1]);
            *(float2*)(C + (row0 + 8) * N + col) = make_float2(acc[mt][nt][2], acc[mt][nt][3]);
        }
    }
}

// ---------------------------------------------------------------------------
// RoPE + round: reads g_qkv, rotates q (scaled) and k, writes fp16 in flash
// layout [bh][S][64]. Thread handles 2 adjacent i (u32 stores).
// ---------------------------------------------------------------------------
__global__ void ropesplit_k(const int* __restrict__ pos)
{
    int idx = blockIdx.x * blockDim.x + threadIdx.x;
    const int total = ROWS * HH * 2 * 16;
    if (idx >= total) return;
    int i2 = (idx & 15) * 2;           // 0,2,..,30
    int rest = idx >> 4;
    int comp = rest & 1; rest >>= 1;   // 0 = q, 1 = k
    int h = rest & 15;
    int row = rest >> 4;
    int b = row >> 11;                 // / SS
    int s = row & (SS - 1);
    int bh = b * HH + h;

    float p = (float)pos[row];
    const float* base = g_qkv + (size_t)row * (3 * DD) + h * TRIPLE + comp * HD;
    float2 x1 = *(const float2*)(base + i2);
    float2 x2 = *(const float2*)(base + i2 + 32);

    float o1a, o2a, o1b, o2b;
    {
        float inv = powf(10000.0f, -(float)i2 * (1.0f / 32.0f));
        float sn, cs; sincosf(p * inv, &sn, &cs);
        o1a = x1.x * cs - x2.x * sn;
        o2a = x1.x * sn + x2.x * cs;
    }
    {
        float inv = powf(10000.0f, -(float)(i2 + 1) * (1.0f / 32.0f));
        float sn, cs; sincosf(p * inv, &sn, &cs);
        o1b = x1.y * cs - x2.y * sn;
        o2b = x1.y * sn + x2.y * cs;
    }
    if (comp == 0) { o1a *= 0.125f; o2a *= 0.125f; o1b *= 0.125f; o2b *= 0.125f; }

    __half* dh = (comp ? g_kh : g_qh) + ((size_t)bh * SS + s) * HD;
    *(uint32_t*)(dh + i2)      = packh(o1a, o1b);
    *(uint32_t*)(dh + i2 + 32) = packh(o2a, o2b);
}

// ---------------------------------------------------------------------------
// V transpose + round: g_qkv v-part -> g_vt [bh][64][S] fp16
// ---------------------------------------------------------------------------
__global__ __launch_bounds__(256) void vsplit_k()
{
    __shared__ float tile[64][65];
    const int bh = blockIdx.x;
    const int b = bh >> 4, h = bh & 15;
    const int s0 = blockIdx.y * 64;
    const int t = threadIdx.x;
#pragma unroll
    for (int i = 0; i < 16; i++) {
        int u = t + i * 256;
        int sl = u >> 6, d = u & 63;
        tile[sl][d] = g_qkv[(size_t)(b * SS + s0 + sl) * (3 * DD) + h * TRIPLE + 2 * HD + d];
    }
    __syncthreads();
#pragma unroll
    for (int i = 0; i < 8; i++) {
        int u = t + i * 256;
        int dl = u >> 5, sl2 = (u & 31) * 2;
        uint32_t v = packh(tile[sl2][dl], tile[sl2 + 1][dl]);
        *(uint32_t*)(g_vt + ((size_t)bh * HD + dl) * SS + s0 + sl2) = v;
    }
}

// ---------------------------------------------------------------------------
// HMMA causal flash attention — fp16 single-term.
// grid (S/128, BH), 256 threads (8 warps, warp = m16 q-tile).
// ---------------------------------------------------------------------------
#define FQ 128
#define FKT 64
#define FSQ 0
#define FSKV 16384
#define FBUF 16384
#define FLASH_SMEM 49152

__device__ __forceinline__ uint32_t fsw(int r, int c) {
    return (uint32_t)((r << 7) + (((c ^ (r & 7))) << 4));
}

__global__ __launch_bounds__(256) void flashmma_k()
{
    extern __shared__ char sm[];
    const uint32_t sb = smem_to_u32(sm);
    const int t = threadIdx.x, lane = t & 31, w = t >> 5;
    const int idx = lane & 7, sel = lane >> 3;
    const int bh = blockIdx.y, b = bh >> 4, h = bh & 15;
    const int qt = (int)gridDim.x - 1 - (int)blockIdx.x;   // heavy tiles first
    const int q0 = qt * FQ;
    const int qw = q0 + w * 16;
    const int ntiles = q0 / FKT + 2;

    // Q tile cp.async
    {
        const __half* s0 = g_qh + ((size_t)bh * SS + q0) * HD;
#pragma unroll
        for (int i = 0; i < 4; i++) {
            int u = t + i * 256; int r = u >> 3, c = u & 7;
            CP_ASYNC16(sb + FSQ + fsw(r, c), s0 + (size_t)r * HD + c * 8);
        }
        CP_COMMIT();
    }

    auto ld_kv = [&](int ct) {
        const int k0 = ct * FKT;
        const uint32_t bd = sb + FSKV + (ct & 1) * FBUF;
        const __half* sk = g_kh + ((size_t)bh * SS + k0) * HD;
#pragma unroll
        for (int i = 0; i < 2; i++) {
            int u = t + i * 256; int r = u >> 3, c = u & 7;
            CP_ASYNC16(bd + fsw(r, c), sk + (size_t)r * HD + c * 8);
        }
        const __half* sv = g_vt + (size_t)bh * HD * SS + k0;
#pragma unroll
        for (int i = 0; i < 2; i++) {
            int u = t + i * 256; int r = u >> 3, c = u & 7;
            CP_ASYNC16(bd + 8192 + fsw(r, c), sv + (size_t)r * SS + c * 8);
        }
        CP_COMMIT();
    };

    ld_kv(0);
    CP_WAIT0();
    __syncthreads();

    // Q fragments (resident): 4 k16 chunks
    uint32_t qf[4][4];
#pragma unroll
    for (int j = 0; j < 4; j++) {
        int row = w * 16 + ((sel & 1) << 3) + idx;
        int ch = 2 * j + (sel >> 1);
        ldsm4(qf[j], sb + FSQ + fsw(row, ch));
    }

    float o[8][4];
#pragma unroll
    for (int nt = 0; nt < 8; nt++)
#pragma unroll
        for (int i = 0; i < 4; i++) o[nt][i] = 0.f;
    float m0 = -INFINITY, m1 = -INFINITY, l0 = 0.f, l1 = 0.f;
    const int r = lane >> 2, cb = (lane & 3) * 2;

    for (int c = 0; c < ntiles; c++) {
        if (c + 1 < ntiles) ld_kv(c + 1);
        const int k0 = c * FKT;
        const uint32_t kb = sb + FSKV + (c & 1) * FBUF;

        if (k0 <= qw + 15) {
            float s[8][4];
#pragma unroll
            for (int nt = 0; nt < 8; nt++)
#pragma unroll
                for (int i = 0; i < 4; i++) s[nt][i] = 0.f;

            // S = Q K^T
#pragma unroll
            for (int j = 0; j < 4; j++) {
                const int krow = ((sel >> 1) << 3) + idx;
                const int kch = 2 * j + (sel & 1);
#pragma unroll
                for (int np = 0; np < 4; np++) {
                    uint32_t th[4];
                    ldsm4(th, kb + fsw(np * 16 + krow, kch));
                    uint32_t b0[2] = { th[0], th[1] }, b1[2] = { th[2], th[3] };
                    mma16816h(s[2 * np],     qf[j], b0);
                    mma16816h(s[2 * np + 1], qf[j], b1);
                }
            }
            // causal mask
            if (k0 + FKT - 1 > qw) {
                const int row0 = qw + r, row1 = row0 + 8;
#pragma unroll
                for (int nt = 0; nt < 8; nt++) {
                    int c0 = k0 + nt * 8 + cb;
                    if (c0 > row0)     s[nt][0] = -INFINITY;
                    if (c0 + 1 > row0) s[nt][1] = -INFINITY;
                    if (c0 > row1)     s[nt][2] = -INFINITY;
                    if (c0 + 1 > row1) s[nt][3] = -INFINITY;
                }
            }
            // online softmax
            float mx0 = s[0][0], mx1 = s[0][2];
#pragma unroll
            for (int nt = 0; nt < 8; nt++) {
                mx0 = fmaxf(mx0, fmaxf(s[nt][0], s[nt][1]));
                mx1 = fmaxf(mx1, fmaxf(s[nt][2], s[nt][3]));
            }
            mx0 = fmaxf(mx0, __shfl_xor_sync(0xffffffffu, mx0, 1));
            mx0 = fmaxf(mx0, __shfl_xor_sync(0xffffffffu, mx0, 2));
            mx1 = fmaxf(mx1, __shfl_xor_sync(0xffffffffu, mx1, 1));
            mx1 = fmaxf(mx1, __shfl_xor_sync(0xffffffffu, mx1, 2));
            float mn0 = fmaxf(m0, mx0), mn1 = fmaxf(m1, mx1);
            float sc0 = __expf(m0 - mn0), sc1 = __expf(m1 - mn1);
            float rs0 = 0.f, rs1 = 0.f;
#pragma unroll
            for (int nt = 0; nt < 8; nt++) {
                s[nt][0] = __expf(s[nt][0] - mn0); rs0 += s[nt][0];
                s[nt][1] = __expf(s[nt][1] - mn0); rs0 += s[nt][1];
                s[nt][2] = __expf(s[nt][2] - mn1); rs1 += s[nt][2];
                s[nt][3] = __expf(s[nt][3] - mn1); rs1 += s[nt][3];
            }
            rs0 += __shfl_xor_sync(0xffffffffu, rs0, 1);
            rs0 += __shfl_xor_sync(0xffffffffu, rs0, 2);
            rs1 += __shfl_xor_sync(0xffffffffu, rs1, 1);
            rs1 += __shfl_xor_sync(0xffffffffu, rs1, 2);
            m0 = mn0; m1 = mn1;
            l0 = l0 * sc0 + rs0; l1 = l1 * sc1 + rs1;
#pragma unroll
            for (int nt = 0; nt < 8; nt++) {
                o[nt][0] *= sc0; o[nt][1] *= sc0;
                o[nt][2] *= sc1; o[nt][3] *= sc1;
            }
            // O += P V (single fp16 P)
#pragma unroll
            for (int j = 0; j < 4; j++) {
                uint32_t pa[4];
                pa[0] = packh(s[2 * j][0],     s[2 * j][1]);
                pa[1] = packh(s[2 * j][2],     s[2 * j][3]);
                pa[2] = packh(s[2 * j + 1][0], s[2 * j + 1][1]);
                pa[3] = packh(s[2 * j + 1][2], s[2 * j + 1][3]);
                const int vrow = ((sel >> 1) << 3) + idx;
                const int vch = 2 * j + (sel & 1);
#pragma unroll
                for (int np = 0; np < 4; np++) {
                    uint32_t th[4];
                    ldsm4(th, kb + 8192 + fsw(np * 16 + vrow, vch));
                    uint32_t b0[2] = { th[0], th[1] }, b1[2] = { th[2], th[3] };
                    mma16816h(o[2 * np],     pa, b0);
                    mma16816h(o[2 * np + 1], pa, b1);
                }
            }
        }
        __syncthreads();
        if (c + 1 < ntiles) { CP_WAIT0(); __syncthreads(); }
    }

    // epilogue: normalize, round to fp16, write g_ch [row][h*64+d]
    float i0 = 1.f / l0, i1 = 1.f / l1;
    const size_t row0 = (size_t)b * SS + qw + r;
    const size_t row1 = row0 + 8;
#pragma unroll
    for (int nt = 0; nt < 8; nt++) {
        int col = h * HD + nt * 8 + cb;
        *(uint32_t*)(g_ch + row0 * DD + col) = packh(o[nt][0] * i0, o[nt][1] * i0);
        *(uint32_t*)(g_ch + row1 * DD + col) = packh(o[nt][2] * i1, o[nt][3] * i1);
    }
}

// ---------------------------------------------------------------------------
// Launch
// Inputs: 0=inputs f32[B,S,D], 1=segment_positions i32[B,S], 2=mask (unused),
// 3=W_in f32[D,3D], 4=W_out f32[D,D]. Output: f32[B,S,D].
// ---------------------------------------------------------------------------
extern "C" void kernel_launch(void* const* d_in, const int* in_sizes, int n_in,
                              void* d_out, int out_size)
{
    const float* x    = (const float*)d_in[0];
    const int*   pos  = (const int*)d_in[1];
    const float* Win  = (const float*)d_in[3];
    const float* Wout = (const float*)d_in[4];
    float* out = (float*)d_out;

    float* qkv;
    __half *ah, *ch, *wT, *oT;
    cudaGetSymbolAddress((void**)&qkv, g_qkv);
    cudaGetSymbolAddress((void**)&ah, g_ah);
    cudaGetSymbolAddress((void**)&ch, g_ch);
    cudaGetSymbolAddress((void**)&wT, g_wT);
    cudaGetSymbolAddress((void**)&oT, g_oT);

    cudaFuncSetAttribute(gemm_hmma_k,
                         cudaFuncAttributeMaxDynamicSharedMemorySize, GEMM_SMEM_SZ);
    cudaFuncSetAttribute(flashmma_k,
                         cudaFuncAttributeMaxDynamicSharedMemorySize, FLASH_SMEM);

    // 0) round inputs to fp16; transpose+round weights to fp16
    {
        int n4 = ROWS * DD / 4;
        cvt_k<<<(n4 + 255) / 256, 256>>>(x, ah, n4);
    }
    tsplit_k<<<dim3(3 * DD / 32, DD / 32), 256>>>(Win, wT, DD, 3 * DD);
    tsplit_k<<<dim3(DD / 32, DD / 32), 256>>>(Wout, oT, DD, DD);

    // 1) QKV projection via fp16 HMMA (KC=64, 2 CTAs/SM)
    gemm_hmma_k<<<dim3(3 * DD / 128, ROWS / 128), 256, GEMM_SMEM_SZ>>>(
        ah, wT, qkv, 3 * DD);

    // 2) RoPE + fp16 round into flash layouts; V transpose+round
    {
        int nrope = ROWS * HH * 2 * 16;
        ropesplit_k<<<(nrope + 255) / 256, 256>>>(pos);
    }
    vsplit_k<<<dim3(BB * HH, SS / 64), 256>>>();

    // 3) HMMA causal flash attention (fp16 single-term; writes fp16 g_ch)
    flashmma_k<<<dim3(SS / FQ, BB * HH), 256, FLASH_SMEM>>>();

    // 4) Output projection via fp16 HMMA
    gemm_hmma_k<<<dim3(DD / 128, ROWS / 128), 256, GEMM_SMEM_SZ>>>(
        ch, oT, out, DD);
}